// round 5
// baseline (speedup 1.0000x reference)
#include <cuda_runtime.h>
#include <math.h>
#include <stdint.h>

#define NTHREADS 256
#define NENS 8
#define HID 64

// Shared-memory float offsets (all 16B aligned)
#define OFF_W1 0                 // 8*6*64  = 3072
#define OFF_B1 3072              // 8*64    = 512
#define OFF_W2 3584              // 8*64*64 = 32768
#define OFF_B2 36352             // 512
#define OFF_W3 36864             // 512
#define OFF_B3 37376             // 8
#define SMEM_FLOATS 37384
#define SMEM_BYTES (SMEM_FLOATS * 4)

// ---- packed fp32x2 primitives (sm_103a FFMA2 — PTX-only) ----
#define FFMA2(d, a, b, c) \
    asm("fma.rn.f32x2 %0, %1, %2, %3;" : "=l"(d) : "l"(a), "l"(b), "l"(c))

__device__ __forceinline__ uint64_t pack2(float v) {
    uint64_t r;
    asm("mov.b64 %0, {%1, %1};" : "=l"(r) : "f"(v));
    return r;
}
__device__ __forceinline__ void unpack2(uint64_t s, float& lo, float& hi) {
    asm("mov.b64 {%0, %1}, %2;" : "=f"(lo), "=f"(hi) : "l"(s));
}

// ---- fast transcendentals: branch-free, MUFU-only, ~1e-6 rel err ----
__device__ __forceinline__ float fast_tanh(float x) {
    float e, r;
    asm("ex2.approx.f32 %0, %1;" : "=f"(e) : "f"(x * 2.8853900817779268f)); // 2*log2(e)
    asm("rcp.approx.f32 %0, %1;" : "=f"(r) : "f"(e + 1.0f));
    return fmaf(-2.0f, r, 1.0f);
}
__device__ __forceinline__ float fast_exp(float x) {
    float e;
    asm("ex2.approx.f32 %0, %1;" : "=f"(e) : "f"(x * 1.4426950408889634f)); // log2(e)
    return e;
}

// Relativistic shock jump (Taub adiabat), gamma = 5/3.
__device__ __forceinline__ void get_vel_shock(
    float pC, float rho, float p, float v, float sign,
    float& rhoC, float& hC, float& vstar, float& Vs)
{
    float h  = 1.0f + 2.5f * p / rho;
    float W  = 1.0f / sqrtf(1.0f - v * v);
    float dp = p - pC;
    float A  = 1.0f + 0.4f * dp / pC;
    float B  = -0.4f * dp / pC;
    float C  = h * dp / rho - h * h;
    float disc = fmaxf(B * B - 4.0f * A * C, 0.0f);
    hC   = (-B + sqrtf(disc)) / (2.0f * A);
    rhoC = 2.5f * pC / (hC - 1.0f);
    float j2   = fmaxf((pC - p) / (h / rho - hC / rhoC), 1e-12f);
    float jabs = sqrtf(j2);
    float rw   = rho * W;
    float a2   = rw * rw;
    Vs = (a2 * v + sign * jabs * sqrtf(j2 + a2 * (1.0f - v * v))) / (a2 + j2);
    float Ws = 1.0f / sqrtf(fmaxf(1.0f - Vs * Vs, 1e-12f));
    float js = sign * jabs;
    vstar = (h * W * v + Ws * (pC - p) / js) /
            (h * W + (pC - p) * (Ws * v / js + 1.0f / (rho * W)));
}

// Flux selection (jnp.where chain, later masks override earlier)
__device__ __forceinline__ void finish_cell(
    const float* __restrict__ F, float* __restrict__ out, int n,
    float bestP, float rho_l, float p_l, float v_l,
    float rho_r, float p_r, float v_r)
{
    float rhoCL, hCL, vstarL, vshL;
    get_vel_shock(bestP, rho_l, p_l, v_l, -1.0f, rhoCL, hCL, vstarL, vshL);
    float rhoCR, hCR, vstarR, vshR;
    get_vel_shock(bestP, rho_r, p_r, v_r,  1.0f, rhoCR, hCR, vstarR, vshR);

    float lam = 0.5f * (vstarR + vstarL);
    float WC  = 1.0f / sqrtf(1.0f - lam * lam);
    float densCL = WC * rhoCL, densCR = WC * rhoCR;

    float f0 = 0.0f, f1 = 0.0f, f2 = 0.0f;
    if (vshL >= 0.0f) {
        f0 = F[n * 6 + 0]; f1 = F[n * 6 + 2]; f2 = F[n * 6 + 4];
    }
    if (vshL < 0.0f && lam > 0.0f) {
        f0 = densCL * lam;
        f1 = densCL * (WC * hCL - 1.0f) * lam;
        f2 = (WC * WC * rhoCL * hCL * lam) * lam + bestP;
    }
    if (lam <= 0.0f && vshR > 0.0f) {
        f0 = densCR * lam;
        f1 = densCR * (WC * hCR - 1.0f) * lam;
        f2 = (WC * WC * rhoCR * hCR * lam) * lam + bestP;
    }
    if (vshR <= 0.0f) {
        f0 = F[n * 6 + 1]; f1 = F[n * 6 + 3]; f2 = F[n * 6 + 5];
    }
    out[n * 3 + 0] = f0;
    out[n * 3 + 1] = f1;
    out[n * 3 + 2] = f2;
}

__global__ void __launch_bounds__(NTHREADS)
shock_solver_kernel(const float* __restrict__ P, const float* __restrict__ F,
                    const float* __restrict__ W1, const float* __restrict__ b1,
                    const float* __restrict__ W2, const float* __restrict__ b2,
                    const float* __restrict__ W3, const float* __restrict__ b3,
                    float* __restrict__ out, int N)
{
    extern __shared__ float smem[];

    for (int i = threadIdx.x; i < 3072;  i += NTHREADS) smem[OFF_W1 + i] = W1[i];
    for (int i = threadIdx.x; i < 512;   i += NTHREADS) smem[OFF_B1 + i] = b1[i];
    for (int i = threadIdx.x; i < 32768; i += NTHREADS) smem[OFF_W2 + i] = W2[i];
    for (int i = threadIdx.x; i < 512;   i += NTHREADS) smem[OFF_B2 + i] = b2[i];
    for (int i = threadIdx.x; i < 512;   i += NTHREADS) smem[OFF_W3 + i] = W3[i];
    for (int i = threadIdx.x; i < 8;     i += NTHREADS) smem[OFF_B3 + i] = b3[i];
    __syncthreads();

    const float* sW1 = smem + OFF_W1;
    const float* sB1 = smem + OFF_B1;
    const float* sW2 = smem + OFF_W2;
    const float* sB2 = smem + OFF_B2;
    const float* sW3 = smem + OFF_W3;
    const float* sB3 = smem + OFF_B3;

    const int stride2 = gridDim.x * NTHREADS * 2;
    for (int n = (blockIdx.x * NTHREADS + threadIdx.x) * 2; n < N; n += stride2) {
        const int nb = n + 1;              // second cell (N = 1e6 is even; guarded anyway)
        const bool has_b = (nb < N);
        const int nb_s = has_b ? nb : n;   // safe index for loads

        // Cell A primitives
        const float rhoLa = P[n * 6 + 0], rhoRa = P[n * 6 + 1];
        const float pLa   = P[n * 6 + 2], pRa   = P[n * 6 + 3];
        const float vLa   = P[n * 6 + 4], vRa   = P[n * 6 + 5];
        // Cell B primitives
        const float rhoLb = P[nb_s * 6 + 0], rhoRb = P[nb_s * 6 + 1];
        const float pLb   = P[nb_s * 6 + 2], pRb   = P[nb_s * 6 + 3];
        const float vLb   = P[nb_s * 6 + 4], vRb   = P[nb_s * 6 + 5];

        uint64_t xa[6], xb[6];
        xa[0] = pack2(logf(rhoLa)); xa[1] = pack2(logf(rhoRa));
        xa[2] = pack2(logf(pLa));   xa[3] = pack2(logf(pRa));
        xa[4] = pack2(vLa);         xa[5] = pack2(vRa);
        xb[0] = pack2(logf(rhoLb)); xb[1] = pack2(logf(rhoRb));
        xb[2] = pack2(logf(pLb));   xb[3] = pack2(logf(pRb));
        xb[4] = pack2(vLb);         xb[5] = pack2(vRb);
        const float aa = fmaxf(pLa, pRa);
        const float ab = fmaxf(pLb, pRb);

        float bestdiff_a = 3.4e38f, bestP_a = 0.0f;
        float bestdiff_b = 3.4e38f, bestP_b = 0.0f;

        for (int e = 0; e < NENS; e++) {
            const float* w1  = sW1 + e * (6 * HID);
            const float* bb1 = sB1 + e * HID;
            const float* w2  = sW2 + e * (HID * HID);
            const float* bb2 = sB2 + e * HID;
            const float* w3  = sW3 + e * HID;

            // ---- Layer 1: both cells share each weight load ----
            float h1a[HID], h1b[HID];
            #pragma unroll
            for (int j = 0; j < HID; j += 8) {
                ulonglong2 bA = *(const ulonglong2*)(bb1 + j);
                ulonglong2 bB = *(const ulonglong2*)(bb1 + j + 4);
                uint64_t sa0 = bA.x, sa1 = bA.y, sa2 = bB.x, sa3 = bB.y;
                uint64_t sb0 = bA.x, sb1 = bA.y, sb2 = bB.x, sb3 = bB.y;
                #pragma unroll
                for (int i = 0; i < 6; i++) {
                    ulonglong2 wA = *(const ulonglong2*)(w1 + i * HID + j);
                    ulonglong2 wB = *(const ulonglong2*)(w1 + i * HID + j + 4);
                    FFMA2(sa0, xa[i], wA.x, sa0);  FFMA2(sb0, xb[i], wA.x, sb0);
                    FFMA2(sa1, xa[i], wA.y, sa1);  FFMA2(sb1, xb[i], wA.y, sb1);
                    FFMA2(sa2, xa[i], wB.x, sa2);  FFMA2(sb2, xb[i], wB.x, sb2);
                    FFMA2(sa3, xa[i], wB.y, sa3);  FFMA2(sb3, xb[i], wB.y, sb3);
                }
                float u0, u1, u2, u3, u4, u5, u6, u7;
                unpack2(sa0, u0, u1); unpack2(sa1, u2, u3);
                unpack2(sa2, u4, u5); unpack2(sa3, u6, u7);
                h1a[j + 0] = fast_tanh(u0); h1a[j + 1] = fast_tanh(u1);
                h1a[j + 2] = fast_tanh(u2); h1a[j + 3] = fast_tanh(u3);
                h1a[j + 4] = fast_tanh(u4); h1a[j + 5] = fast_tanh(u5);
                h1a[j + 6] = fast_tanh(u6); h1a[j + 7] = fast_tanh(u7);
                unpack2(sb0, u0, u1); unpack2(sb1, u2, u3);
                unpack2(sb2, u4, u5); unpack2(sb3, u6, u7);
                h1b[j + 0] = fast_tanh(u0); h1b[j + 1] = fast_tanh(u1);
                h1b[j + 2] = fast_tanh(u2); h1b[j + 3] = fast_tanh(u3);
                h1b[j + 4] = fast_tanh(u4); h1b[j + 5] = fast_tanh(u5);
                h1b[j + 6] = fast_tanh(u6); h1b[j + 7] = fast_tanh(u7);
            }

            // ---- Layers 2+3 fused: each LDS.128 feeds 8 FFMA2 (2 cells) ----
            float acca = sB3[e];
            float accb = acca;
            for (int j = 0; j < HID; j += 8) {   // runtime loop (I-cache)
                ulonglong2 bA = *(const ulonglong2*)(bb2 + j);
                ulonglong2 bB = *(const ulonglong2*)(bb2 + j + 4);
                uint64_t sa0 = bA.x, sa1 = bA.y, sa2 = bB.x, sa3 = bB.y;
                uint64_t sb0 = bA.x, sb1 = bA.y, sb2 = bB.x, sb3 = bB.y;
                #pragma unroll
                for (int k = 0; k < HID; k++) {
                    uint64_t ha = pack2(h1a[k]);
                    uint64_t hb = pack2(h1b[k]);
                    ulonglong2 wA = *(const ulonglong2*)(w2 + k * HID + j);
                    ulonglong2 wB = *(const ulonglong2*)(w2 + k * HID + j + 4);
                    FFMA2(sa0, ha, wA.x, sa0);  FFMA2(sb0, hb, wA.x, sb0);
                    FFMA2(sa1, ha, wA.y, sa1);  FFMA2(sb1, hb, wA.y, sb1);
                    FFMA2(sa2, ha, wB.x, sa2);  FFMA2(sb2, hb, wB.x, sb2);
                    FFMA2(sa3, ha, wB.y, sa3);  FFMA2(sb3, hb, wB.y, sb3);
                }
                float4 wvA = *(const float4*)(w3 + j);
                float4 wvB = *(const float4*)(w3 + j + 4);
                float u0, u1, u2, u3, u4, u5, u6, u7;
                unpack2(sa0, u0, u1); unpack2(sa1, u2, u3);
                unpack2(sa2, u4, u5); unpack2(sa3, u6, u7);
                acca += fast_tanh(u0) * wvA.x + fast_tanh(u1) * wvA.y
                      + fast_tanh(u2) * wvA.z + fast_tanh(u3) * wvA.w
                      + fast_tanh(u4) * wvB.x + fast_tanh(u5) * wvB.y
                      + fast_tanh(u6) * wvB.z + fast_tanh(u7) * wvB.w;
                unpack2(sb0, u0, u1); unpack2(sb1, u2, u3);
                unpack2(sb2, u4, u5); unpack2(sb3, u6, u7);
                accb += fast_tanh(u0) * wvA.x + fast_tanh(u1) * wvA.y
                      + fast_tanh(u2) * wvA.z + fast_tanh(u3) * wvA.w
                      + fast_tanh(u4) * wvB.x + fast_tanh(u5) * wvB.y
                      + fast_tanh(u6) * wvB.z + fast_tanh(u7) * wvB.w;
            }

            // pressC = a*(1 + 2*exp(z))  [== a*(1+sigmoid)/(1-sigmoid)]
            float pca = aa * (1.0f + 2.0f * fast_exp(acca));
            float pcb = ab * (1.0f + 2.0f * fast_exp(accb));

            float rC, hC, VsL, VsR, vsLa, vsRa, vsLb, vsRb;
            get_vel_shock(pca, rhoLa, pLa, vLa, -1.0f, rC, hC, vsLa, VsL);
            get_vel_shock(pca, rhoRa, pRa, vRa,  1.0f, rC, hC, vsRa, VsR);
            float da = fabsf(vsLa - vsRa);
            if (da < bestdiff_a) { bestdiff_a = da; bestP_a = pca; }

            get_vel_shock(pcb, rhoLb, pLb, vLb, -1.0f, rC, hC, vsLb, VsL);
            get_vel_shock(pcb, rhoRb, pRb, vRb,  1.0f, rC, hC, vsRb, VsR);
            float db = fabsf(vsLb - vsRb);
            if (db < bestdiff_b) { bestdiff_b = db; bestP_b = pcb; }
        }

        finish_cell(F, out, n, bestP_a, rhoLa, pLa, vLa, rhoRa, pRa, vRa);
        if (has_b)
            finish_cell(F, out, nb, bestP_b, rhoLb, pLb, vLb, rhoRb, pRb, vRb);
    }
}

extern "C" void kernel_launch(void* const* d_in, const int* in_sizes, int n_in,
                              void* d_out, int out_size)
{
    const float* P  = (const float*)d_in[0];
    const float* F  = (const float*)d_in[2];
    const float* W1 = (const float*)d_in[5];
    const float* b1 = (const float*)d_in[6];
    const float* W2 = (const float*)d_in[7];
    const float* b2 = (const float*)d_in[8];
    const float* W3 = (const float*)d_in[9];
    const float* b3 = (const float*)d_in[10];
    float* out = (float*)d_out;
    const int N = in_sizes[0] / 6;

    cudaFuncSetAttribute(shock_solver_kernel,
                         cudaFuncAttributeMaxDynamicSharedMemorySize, SMEM_BYTES);

    shock_solver_kernel<<<148, NTHREADS, SMEM_BYTES>>>(
        P, F, W1, b1, W2, b2, W3, b3, out, N);
}

// round 6
// speedup vs baseline: 1.2237x; 1.2237x over previous
#include <cuda_runtime.h>
#include <cuda_bf16.h>
#include <math.h>
#include <stdint.h>

#define NTHREADS 256
#define NWARPS   (NTHREADS/32)
#define NENS 8
#define HID 64

// padded K-strides (in bf16 halves) for transposed weight tiles
#define W1K 18   // layer1: k = 0..15 (6 real, rest zero), padded stride 18
#define W2K 72   // layer2: k = 0..63 (+8 zero pad), stride 72 -> conflict-free B-frag LDS

// __device__ scratch (allocation-free): bf16 hi/lo splits of transposed weights
__device__ __align__(16) __nv_bfloat16 g_w1t_hi[NENS * HID * W1K];
__device__ __align__(16) __nv_bfloat16 g_w1t_lo[NENS * HID * W1K];
__device__ __align__(16) __nv_bfloat16 g_w2t_hi[NENS * HID * W2K];
__device__ __align__(16) __nv_bfloat16 g_w2t_lo[NENS * HID * W2K];

// ---- shared memory byte offsets ----
#define SM_W2HI 0
#define SM_W2LO (SM_W2HI + NENS*HID*W2K*2)          // 73728
#define SM_W1HI (SM_W2LO + NENS*HID*W2K*2)          // 147456
#define SM_W1LO (SM_W1HI + NENS*HID*W1K*2)          // 165888
#define SM_B1   (SM_W1LO + NENS*HID*W1K*2)          // 184320
#define SM_B2   (SM_B1 + NENS*HID*4)                // 186368
#define SM_W3   (SM_B2 + NENS*HID*4)                // 188416
#define SM_B3   (SM_W3 + NENS*HID*4)                // 190464
#define SM_X    (SM_B3 + 32)                        // 190496
#define SMEM_BYTES (SM_X + NWARPS*16*8*4)           // 194592

// ---- fast transcendentals (proven: final rel_err 2.5e-7) ----
__device__ __forceinline__ float fast_tanh(float x) {
    float e, r;
    asm("ex2.approx.f32 %0, %1;" : "=f"(e) : "f"(x * 2.8853900817779268f));
    asm("rcp.approx.f32 %0, %1;" : "=f"(r) : "f"(e + 1.0f));
    return fmaf(-2.0f, r, 1.0f);
}
__device__ __forceinline__ float fast_exp(float x) {
    float e;
    asm("ex2.approx.f32 %0, %1;" : "=f"(e) : "f"(x * 1.4426950408889634f));
    return e;
}

// ---- bf16x2 pack + hi/lo split: v = hi + lo (each bf16), err ~2^-18 ----
__device__ __forceinline__ void split2(float v0, float v1, uint32_t& hi, uint32_t& lo) {
    __nv_bfloat162 h = __floats2bfloat162_rn(v0, v1);   // .x (low half) = v0
    hi = *reinterpret_cast<uint32_t*>(&h);
    float f0 = __uint_as_float(hi << 16);
    float f1 = __uint_as_float(hi & 0xffff0000u);
    __nv_bfloat162 l = __floats2bfloat162_rn(v0 - f0, v1 - f1);
    lo = *reinterpret_cast<uint32_t*>(&l);
}

// ---- mma.sync m16n8k16 bf16, fp32 accum (HMMA) ----
__device__ __forceinline__ void mma16816(float& c0, float& c1, float& c2, float& c3,
    uint32_t a0, uint32_t a1, uint32_t a2, uint32_t a3, uint32_t b0, uint32_t b1)
{
    asm volatile("mma.sync.aligned.m16n8k16.row.col.f32.bf16.bf16.f32 "
        "{%0,%1,%2,%3},{%4,%5,%6,%7},{%8,%9},{%0,%1,%2,%3};"
        : "+f"(c0), "+f"(c1), "+f"(c2), "+f"(c3)
        : "r"(a0), "r"(a1), "r"(a2), "r"(a3), "r"(b0), "r"(b1));
}

// Relativistic shock jump (Taub adiabat), gamma = 5/3.
__device__ __forceinline__ void get_vel_shock(
    float pC, float rho, float p, float v, float sign,
    float& rhoC, float& hC, float& vstar, float& Vs)
{
    float h  = 1.0f + 2.5f * p / rho;
    float W  = 1.0f / sqrtf(1.0f - v * v);
    float dp = p - pC;
    float A  = 1.0f + 0.4f * dp / pC;
    float B  = -0.4f * dp / pC;
    float C  = h * dp / rho - h * h;
    float disc = fmaxf(B * B - 4.0f * A * C, 0.0f);
    hC   = (-B + sqrtf(disc)) / (2.0f * A);
    rhoC = 2.5f * pC / (hC - 1.0f);
    float j2   = fmaxf((pC - p) / (h / rho - hC / rhoC), 1e-12f);
    float jabs = sqrtf(j2);
    float rw   = rho * W;
    float a2   = rw * rw;
    Vs = (a2 * v + sign * jabs * sqrtf(j2 + a2 * (1.0f - v * v))) / (a2 + j2);
    float Ws = 1.0f / sqrtf(fmaxf(1.0f - Vs * Vs, 1e-12f));
    float js = sign * jabs;
    vstar = (h * W * v + Ws * (pC - p) / js) /
            (h * W + (pC - p) * (Ws * v / js + 1.0f / (rho * W)));
}

__device__ __forceinline__ void finish_cell(
    const float* __restrict__ F, float* __restrict__ out, int n,
    float bestP, float rho_l, float p_l, float v_l,
    float rho_r, float p_r, float v_r)
{
    float rhoCL, hCL, vstarL, vshL;
    get_vel_shock(bestP, rho_l, p_l, v_l, -1.0f, rhoCL, hCL, vstarL, vshL);
    float rhoCR, hCR, vstarR, vshR;
    get_vel_shock(bestP, rho_r, p_r, v_r,  1.0f, rhoCR, hCR, vstarR, vshR);

    float lam = 0.5f * (vstarR + vstarL);
    float WC  = 1.0f / sqrtf(1.0f - lam * lam);
    float densCL = WC * rhoCL, densCR = WC * rhoCR;

    float f0 = 0.0f, f1 = 0.0f, f2 = 0.0f;
    if (vshL >= 0.0f) { f0 = F[n*6+0]; f1 = F[n*6+2]; f2 = F[n*6+4]; }
    if (vshL < 0.0f && lam > 0.0f) {
        f0 = densCL * lam;
        f1 = densCL * (WC * hCL - 1.0f) * lam;
        f2 = (WC * WC * rhoCL * hCL * lam) * lam + bestP;
    }
    if (lam <= 0.0f && vshR > 0.0f) {
        f0 = densCR * lam;
        f1 = densCR * (WC * hCR - 1.0f) * lam;
        f2 = (WC * WC * rhoCR * hCR * lam) * lam + bestP;
    }
    if (vshR <= 0.0f) { f0 = F[n*6+1]; f1 = F[n*6+3]; f2 = F[n*6+5]; }
    out[n*3+0] = f0; out[n*3+1] = f1; out[n*3+2] = f2;
}

// ---- prep: build transposed, padded, bf16 hi/lo weight tables ----
__global__ void prep_kernel(const float* __restrict__ W1, const float* __restrict__ W2)
{
    const int n1 = NENS * HID * W1K;
    const int n2 = NENS * HID * W2K;
    int idx = blockIdx.x * blockDim.x + threadIdx.x;
    if (idx < n1) {
        int k = idx % W1K, n = (idx / W1K) % HID, e = idx / (W1K * HID);
        float w = (k < 6) ? W1[(e*6 + k)*HID + n] : 0.0f;
        __nv_bfloat16 h = __float2bfloat16(w);
        g_w1t_hi[idx] = h;
        g_w1t_lo[idx] = __float2bfloat16(w - __bfloat162float(h));
    } else if (idx < n1 + n2) {
        int j = idx - n1;
        int k = j % W2K, n = (j / W2K) % HID, e = j / (W2K * HID);
        float w = (k < HID) ? W2[(e*HID + k)*HID + n] : 0.0f;
        __nv_bfloat16 h = __float2bfloat16(w);
        g_w2t_hi[j] = h;
        g_w2t_lo[j] = __float2bfloat16(w - __bfloat162float(h));
    }
}

__global__ void __launch_bounds__(NTHREADS)
solver_mma(const float* __restrict__ P, const float* __restrict__ F,
           const float* __restrict__ b1g, const float* __restrict__ b2g,
           const float* __restrict__ w3g, const float* __restrict__ b3g,
           float* __restrict__ out, int N)
{
    extern __shared__ char smem[];
    __nv_bfloat16* sW2hi = (__nv_bfloat16*)(smem + SM_W2HI);
    __nv_bfloat16* sW2lo = (__nv_bfloat16*)(smem + SM_W2LO);
    __nv_bfloat16* sW1hi = (__nv_bfloat16*)(smem + SM_W1HI);
    __nv_bfloat16* sW1lo = (__nv_bfloat16*)(smem + SM_W1LO);
    float* sB1 = (float*)(smem + SM_B1);
    float* sB2 = (float*)(smem + SM_B2);
    float* sW3 = (float*)(smem + SM_W3);
    float* sB3 = (float*)(smem + SM_B3);
    float* sX  = (float*)(smem + SM_X);

    // cooperative smem fill
    {
        const int4* s1 = (const int4*)g_w2t_hi;  int4* d1 = (int4*)sW2hi;
        const int4* s2 = (const int4*)g_w2t_lo;  int4* d2 = (int4*)sW2lo;
        for (int i = threadIdx.x; i < NENS*HID*W2K*2/16; i += NTHREADS) { d1[i] = s1[i]; d2[i] = s2[i]; }
        const int4* s3 = (const int4*)g_w1t_hi;  int4* d3 = (int4*)sW1hi;
        const int4* s4 = (const int4*)g_w1t_lo;  int4* d4 = (int4*)sW1lo;
        for (int i = threadIdx.x; i < NENS*HID*W1K*2/16; i += NTHREADS) { d3[i] = s3[i]; d4[i] = s4[i]; }
        for (int i = threadIdx.x; i < NENS*HID; i += NTHREADS) {
            sB1[i] = b1g[i]; sB2[i] = b2g[i]; sW3[i] = w3g[i];
        }
        if (threadIdx.x < NENS) sB3[threadIdx.x] = b3g[threadIdx.x];
    }
    __syncthreads();

    const int lane = threadIdx.x & 31, wid = threadIdx.x >> 5;
    const int g = lane >> 2, t = lane & 3;
    const int ntiles = (N + 15) >> 4;
    float* Xw = sX + wid * 128;

    for (int tile = blockIdx.x * NWARPS + wid; tile < ntiles; tile += gridDim.x * NWARPS) {
        const int cell = tile * 16 + lane;
        float rl = 1.f, rr = 1.f, pl = 1.f, pr = 1.f, vl = 0.f, vr = 0.f, aPress = 1.f;
        if (lane < 16) {
            if (cell < N) {
                rl = P[cell*6+0]; rr = P[cell*6+1];
                pl = P[cell*6+2]; pr = P[cell*6+3];
                vl = P[cell*6+4]; vr = P[cell*6+5];
                Xw[lane*8+0] = logf(rl); Xw[lane*8+1] = logf(rr);
                Xw[lane*8+2] = logf(pl); Xw[lane*8+3] = logf(pr);
                Xw[lane*8+4] = vl;       Xw[lane*8+5] = vr;
                Xw[lane*8+6] = 0.f;      Xw[lane*8+7] = 0.f;
                aPress = fmaxf(pl, pr);
            } else {
                #pragma unroll
                for (int f = 0; f < 8; f++) Xw[lane*8+f] = 0.f;
            }
        }
        __syncwarp();

        // layer1 A-fragments (rows = cells g, g+8; k = 2t,2t+1; k>=8 -> zero regs)
        uint32_t a1h0, a1l0, a1h1, a1l1;
        {
            float2 f  = *(float2*)&Xw[g*8 + 2*t];
            float2 f8 = *(float2*)&Xw[(g+8)*8 + 2*t];
            split2(f.x,  f.y,  a1h0, a1l0);
            split2(f8.x, f8.y, a1h1, a1l1);
        }
        __syncwarp();   // reads done before next iteration's stores

        float bestdiff = 3.4e38f, bestP = 0.f;

        for (int e = 0; e < NENS; e++) {
            // ---- layer 1: X[16x16] @ W1[16x64] -> h1, kept as layer-2 A-frags ----
            uint32_t A2h[4][4], A2l[4][4];
            const __nv_bfloat16* w1h = sW1hi + (e * HID) * W1K;
            const __nv_bfloat16* w1l = sW1lo + (e * HID) * W1K;
            #pragma unroll
            for (int nt = 0; nt < 8; nt++) {
                float c0 = 0.f, c1 = 0.f, c2 = 0.f, c3 = 0.f;
                int row = nt * 8 + g;
                uint32_t bh = *(const uint32_t*)(w1h + row * W1K + 2*t);
                uint32_t bl = *(const uint32_t*)(w1l + row * W1K + 2*t);
                mma16816(c0,c1,c2,c3, a1h0,a1h1, 0u,0u, bh, 0u);
                mma16816(c0,c1,c2,c3, a1h0,a1h1, 0u,0u, bl, 0u);
                mma16816(c0,c1,c2,c3, a1l0,a1l1, 0u,0u, bh, 0u);
                float2 bias = *(float2*)&sB1[e*HID + nt*8 + 2*t];
                float th0 = fast_tanh(c0 + bias.x);
                float th1 = fast_tanh(c1 + bias.y);
                float th2 = fast_tanh(c2 + bias.x);
                float th3 = fast_tanh(c3 + bias.y);
                // C->A remap: tile nt feeds A k-tile nt/2, regs (nt&1)*2, +1
                int kt = nt >> 1, hh = (nt & 1) * 2;
                split2(th0, th1, A2h[kt][hh],     A2l[kt][hh]);
                split2(th2, th3, A2h[kt][hh + 1], A2l[kt][hh + 1]);
            }

            // ---- layers 2+3: h1[16x64] @ W2[64x64], tanh, dot W3 ----
            float zp0 = 0.f, zp1 = 0.f;
            const __nv_bfloat16* w2h = sW2hi + (e * HID) * W2K;
            const __nv_bfloat16* w2l = sW2lo + (e * HID) * W2K;
            for (int nt = 0; nt < 8; nt++) {            // runtime loop (I-cache)
                float c0 = 0.f, c1 = 0.f, c2 = 0.f, c3 = 0.f;
                const __nv_bfloat16* rh = w2h + (nt*8 + g) * W2K + 2*t;
                const __nv_bfloat16* rl2 = w2l + (nt*8 + g) * W2K + 2*t;
                #pragma unroll
                for (int kt = 0; kt < 4; kt++) {
                    uint32_t bh0 = *(const uint32_t*)(rh  + kt*16);
                    uint32_t bh1 = *(const uint32_t*)(rh  + kt*16 + 8);
                    uint32_t bl0 = *(const uint32_t*)(rl2 + kt*16);
                    uint32_t bl1 = *(const uint32_t*)(rl2 + kt*16 + 8);
                    mma16816(c0,c1,c2,c3, A2h[kt][0],A2h[kt][1],A2h[kt][2],A2h[kt][3], bh0,bh1);
                    mma16816(c0,c1,c2,c3, A2h[kt][0],A2h[kt][1],A2h[kt][2],A2h[kt][3], bl0,bl1);
                    mma16816(c0,c1,c2,c3, A2l[kt][0],A2l[kt][1],A2l[kt][2],A2l[kt][3], bh0,bh1);
                }
                float2 bias = *(float2*)&sB2[e*HID + nt*8 + 2*t];
                float2 wv   = *(float2*)&sW3[e*HID + nt*8 + 2*t];
                float th0 = fast_tanh(c0 + bias.x), th1 = fast_tanh(c1 + bias.y);
                float th2 = fast_tanh(c2 + bias.x), th3 = fast_tanh(c3 + bias.y);
                zp0 += th0 * wv.x + th1 * wv.y;
                zp1 += th2 * wv.x + th3 * wv.y;
            }
            // reduce over the 4 lanes of each row-group
            zp0 += __shfl_xor_sync(0xffffffffu, zp0, 1);
            zp0 += __shfl_xor_sync(0xffffffffu, zp0, 2);
            zp1 += __shfl_xor_sync(0xffffffffu, zp1, 1);
            zp1 += __shfl_xor_sync(0xffffffffu, zp1, 2);
            int src = (lane & 7) * 4;
            float za = __shfl_sync(0xffffffffu, zp0, src);
            float zb = __shfl_sync(0xffffffffu, zp1, src);

            if (lane < 16 && cell < N) {
                float z = ((lane < 8) ? za : zb) + sB3[e];
                float pc = aPress * (1.0f + 2.0f * fast_exp(z));
                float rC, hC, vsl, Vs1, vsr, Vs2;
                get_vel_shock(pc, rl, pl, vl, -1.0f, rC, hC, vsl, Vs1);
                get_vel_shock(pc, rr, pr, vr,  1.0f, rC, hC, vsr, Vs2);
                float d = fabsf(vsl - vsr);
                if (d < bestdiff) { bestdiff = d; bestP = pc; }
            }
        }

        if (lane < 16 && cell < N)
            finish_cell(F, out, cell, bestP, rl, pl, vl, rr, pr, vr);
    }
}

extern "C" void kernel_launch(void* const* d_in, const int* in_sizes, int n_in,
                              void* d_out, int out_size)
{
    const float* P  = (const float*)d_in[0];
    const float* F  = (const float*)d_in[2];
    const float* W1 = (const float*)d_in[5];
    const float* b1 = (const float*)d_in[6];
    const float* W2 = (const float*)d_in[7];
    const float* b2 = (const float*)d_in[8];
    const float* W3 = (const float*)d_in[9];
    const float* b3 = (const float*)d_in[10];
    float* out = (float*)d_out;
    const int N = in_sizes[0] / 6;

    const int nprep = NENS*HID*W1K + NENS*HID*W2K;
    prep_kernel<<<(nprep + 255) / 256, 256>>>(W1, W2);

    cudaFuncSetAttribute(solver_mma,
                         cudaFuncAttributeMaxDynamicSharedMemorySize, SMEM_BYTES);
    solver_mma<<<148, NTHREADS, SMEM_BYTES>>>(P, F, b1, b2, W3, b3, out, N);
}

// round 7
// speedup vs baseline: 1.5460x; 1.2634x over previous
#include <cuda_runtime.h>
#include <cuda_bf16.h>
#include <math.h>
#include <stdint.h>

#define NTHREADS 512
#define NWARPS   (NTHREADS/32)
#define NENS 8
#define HID 64

// padded K-strides (in bf16 halves) for transposed weight tiles
#define W1K 18   // layer1: k = 0..15 (6 real, rest zero), padded stride 18
#define W2K 72   // layer2: k = 0..63 (+8 zero pad), stride 72 -> conflict-free B-frag LDS

// __device__ scratch (allocation-free): bf16 hi/lo splits of transposed weights
__device__ __align__(16) __nv_bfloat16 g_w1t_hi[NENS * HID * W1K];
__device__ __align__(16) __nv_bfloat16 g_w1t_lo[NENS * HID * W1K];
__device__ __align__(16) __nv_bfloat16 g_w2t_hi[NENS * HID * W2K];
__device__ __align__(16) __nv_bfloat16 g_w2t_lo[NENS * HID * W2K];

// ---- shared memory byte offsets ----
#define SM_W2HI 0
#define SM_W2LO (SM_W2HI + NENS*HID*W2K*2)          // 73728
#define SM_W1HI (SM_W2LO + NENS*HID*W2K*2)          // 147456
#define SM_W1LO (SM_W1HI + NENS*HID*W1K*2)          // 165888
#define SM_B1   (SM_W1LO + NENS*HID*W1K*2)          // 184320
#define SM_B2   (SM_B1 + NENS*HID*4)                // 186368
#define SM_W3   (SM_B2 + NENS*HID*4)                // 188416
#define SM_B3   (SM_W3 + NENS*HID*4)                // 190464
#define SM_X    (SM_B3 + 32)                        // 190496
#define SMEM_BYTES (SM_X + NWARPS*16*8*4)           // 198688

// ---- fast transcendentals ----
__device__ __forceinline__ float fast_tanh(float x) {
    float e, r;
    asm("ex2.approx.f32 %0, %1;" : "=f"(e) : "f"(x * 2.8853900817779268f));
    asm("rcp.approx.f32 %0, %1;" : "=f"(r) : "f"(e + 1.0f));
    return fmaf(-2.0f, r, 1.0f);
}
__device__ __forceinline__ float fast_exp(float x) {
    float e;
    asm("ex2.approx.f32 %0, %1;" : "=f"(e) : "f"(x * 1.4426950408889634f));
    return e;
}

// ---- bf16x2 pack + hi/lo split: v = hi + lo (each bf16), err ~2^-18 ----
__device__ __forceinline__ void split2(float v0, float v1, uint32_t& hi, uint32_t& lo) {
    __nv_bfloat162 h = __floats2bfloat162_rn(v0, v1);   // .x (low half) = v0
    hi = *reinterpret_cast<uint32_t*>(&h);
    float f0 = __uint_as_float(hi << 16);
    float f1 = __uint_as_float(hi & 0xffff0000u);
    __nv_bfloat162 l = __floats2bfloat162_rn(v0 - f0, v1 - f1);
    lo = *reinterpret_cast<uint32_t*>(&l);
}

// ---- mma.sync m16n8k16 bf16, fp32 accum (HMMA) ----
__device__ __forceinline__ void mma16816(float& c0, float& c1, float& c2, float& c3,
    uint32_t a0, uint32_t a1, uint32_t a2, uint32_t a3, uint32_t b0, uint32_t b1)
{
    asm volatile("mma.sync.aligned.m16n8k16.row.col.f32.bf16.bf16.f32 "
        "{%0,%1,%2,%3},{%4,%5,%6,%7},{%8,%9},{%0,%1,%2,%3};"
        : "+f"(c0), "+f"(c1), "+f"(c2), "+f"(c3)
        : "r"(a0), "r"(a1), "r"(a2), "r"(a3), "r"(b0), "r"(b1));
}

// Relativistic shock jump (Taub adiabat), gamma = 5/3.
__device__ __forceinline__ void get_vel_shock(
    float pC, float rho, float p, float v, float sign,
    float& rhoC, float& hC, float& vstar, float& Vs)
{
    float h  = 1.0f + 2.5f * p / rho;
    float W  = 1.0f / sqrtf(1.0f - v * v);
    float dp = p - pC;
    float A  = 1.0f + 0.4f * dp / pC;
    float B  = -0.4f * dp / pC;
    float C  = h * dp / rho - h * h;
    float disc = fmaxf(B * B - 4.0f * A * C, 0.0f);
    hC   = (-B + sqrtf(disc)) / (2.0f * A);
    rhoC = 2.5f * pC / (hC - 1.0f);
    float j2   = fmaxf((pC - p) / (h / rho - hC / rhoC), 1e-12f);
    float jabs = sqrtf(j2);
    float rw   = rho * W;
    float a2   = rw * rw;
    Vs = (a2 * v + sign * jabs * sqrtf(j2 + a2 * (1.0f - v * v))) / (a2 + j2);
    float Ws = 1.0f / sqrtf(fmaxf(1.0f - Vs * Vs, 1e-12f));
    float js = sign * jabs;
    vstar = (h * W * v + Ws * (pC - p) / js) /
            (h * W + (pC - p) * (Ws * v / js + 1.0f / (rho * W)));
}

__device__ __forceinline__ void finish_cell(
    const float* __restrict__ F, float* __restrict__ out, int n,
    float bestP, float rho_l, float p_l, float v_l,
    float rho_r, float p_r, float v_r)
{
    float rhoCL, hCL, vstarL, vshL;
    get_vel_shock(bestP, rho_l, p_l, v_l, -1.0f, rhoCL, hCL, vstarL, vshL);
    float rhoCR, hCR, vstarR, vshR;
    get_vel_shock(bestP, rho_r, p_r, v_r,  1.0f, rhoCR, hCR, vstarR, vshR);

    float lam = 0.5f * (vstarR + vstarL);
    float WC  = 1.0f / sqrtf(1.0f - lam * lam);
    float densCL = WC * rhoCL, densCR = WC * rhoCR;

    float f0 = 0.0f, f1 = 0.0f, f2 = 0.0f;
    if (vshL >= 0.0f) { f0 = F[n*6+0]; f1 = F[n*6+2]; f2 = F[n*6+4]; }
    if (vshL < 0.0f && lam > 0.0f) {
        f0 = densCL * lam;
        f1 = densCL * (WC * hCL - 1.0f) * lam;
        f2 = (WC * WC * rhoCL * hCL * lam) * lam + bestP;
    }
    if (lam <= 0.0f && vshR > 0.0f) {
        f0 = densCR * lam;
        f1 = densCR * (WC * hCR - 1.0f) * lam;
        f2 = (WC * WC * rhoCR * hCR * lam) * lam + bestP;
    }
    if (vshR <= 0.0f) { f0 = F[n*6+1]; f1 = F[n*6+3]; f2 = F[n*6+5]; }
    out[n*3+0] = f0; out[n*3+1] = f1; out[n*3+2] = f2;
}

// ---- prep: build transposed, padded, bf16 hi/lo weight tables ----
__global__ void prep_kernel(const float* __restrict__ W1, const float* __restrict__ W2)
{
    const int n1 = NENS * HID * W1K;
    const int n2 = NENS * HID * W2K;
    int idx = blockIdx.x * blockDim.x + threadIdx.x;
    if (idx < n1) {
        int k = idx % W1K, n = (idx / W1K) % HID, e = idx / (W1K * HID);
        float w = (k < 6) ? W1[(e*6 + k)*HID + n] : 0.0f;
        __nv_bfloat16 h = __float2bfloat16(w);
        g_w1t_hi[idx] = h;
        g_w1t_lo[idx] = __float2bfloat16(w - __bfloat162float(h));
    } else if (idx < n1 + n2) {
        int j = idx - n1;
        int k = j % W2K, n = (j / W2K) % HID, e = j / (W2K * HID);
        float w = (k < HID) ? W2[(e*HID + k)*HID + n] : 0.0f;
        __nv_bfloat16 h = __float2bfloat16(w);
        g_w2t_hi[j] = h;
        g_w2t_lo[j] = __float2bfloat16(w - __bfloat162float(h));
    }
}

__global__ void __launch_bounds__(NTHREADS)
solver_mma(const float* __restrict__ P, const float* __restrict__ F,
           const float* __restrict__ b1g, const float* __restrict__ b2g,
           const float* __restrict__ w3g, const float* __restrict__ b3g,
           float* __restrict__ out, int N)
{
    extern __shared__ char smem[];
    __nv_bfloat16* sW2hi = (__nv_bfloat16*)(smem + SM_W2HI);
    __nv_bfloat16* sW2lo = (__nv_bfloat16*)(smem + SM_W2LO);
    __nv_bfloat16* sW1hi = (__nv_bfloat16*)(smem + SM_W1HI);
    __nv_bfloat16* sW1lo = (__nv_bfloat16*)(smem + SM_W1LO);
    float* sB1 = (float*)(smem + SM_B1);
    float* sB2 = (float*)(smem + SM_B2);
    float* sW3 = (float*)(smem + SM_W3);
    float* sB3 = (float*)(smem + SM_B3);
    float* sX  = (float*)(smem + SM_X);

    // cooperative smem fill
    {
        const int4* s1 = (const int4*)g_w2t_hi;  int4* d1 = (int4*)sW2hi;
        const int4* s2 = (const int4*)g_w2t_lo;  int4* d2 = (int4*)sW2lo;
        for (int i = threadIdx.x; i < NENS*HID*W2K*2/16; i += NTHREADS) { d1[i] = s1[i]; d2[i] = s2[i]; }
        const int4* s3 = (const int4*)g_w1t_hi;  int4* d3 = (int4*)sW1hi;
        const int4* s4 = (const int4*)g_w1t_lo;  int4* d4 = (int4*)sW1lo;
        for (int i = threadIdx.x; i < NENS*HID*W1K*2/16; i += NTHREADS) { d3[i] = s3[i]; d4[i] = s4[i]; }
        for (int i = threadIdx.x; i < NENS*HID; i += NTHREADS) {
            sB1[i] = b1g[i]; sB2[i] = b2g[i]; sW3[i] = w3g[i];
        }
        if (threadIdx.x < NENS) sB3[threadIdx.x] = b3g[threadIdx.x];
    }
    __syncthreads();

    const int lane = threadIdx.x & 31, wid = threadIdx.x >> 5;
    const int g = lane >> 2, t = lane & 3;
    const int ntiles = (N + 15) >> 4;
    float* Xw = sX + wid * 128;

    for (int tile = blockIdx.x * NWARPS + wid; tile < ntiles; tile += gridDim.x * NWARPS) {
        const int cell = tile * 16 + lane;
        float rl = 1.f, rr = 1.f, pl = 1.f, pr = 1.f, vl = 0.f, vr = 0.f, aPress = 1.f;
        if (lane < 16) {
            if (cell < N) {
                rl = P[cell*6+0]; rr = P[cell*6+1];
                pl = P[cell*6+2]; pr = P[cell*6+3];
                vl = P[cell*6+4]; vr = P[cell*6+5];
                Xw[lane*8+0] = logf(rl); Xw[lane*8+1] = logf(rr);
                Xw[lane*8+2] = logf(pl); Xw[lane*8+3] = logf(pr);
                Xw[lane*8+4] = vl;       Xw[lane*8+5] = vr;
                Xw[lane*8+6] = 0.f;      Xw[lane*8+7] = 0.f;
                aPress = fmaxf(pl, pr);
            } else {
                #pragma unroll
                for (int f = 0; f < 8; f++) Xw[lane*8+f] = 0.f;
            }
        }
        __syncwarp();

        // layer1 A-fragments (rows = cells g, g+8; k = 2t,2t+1; k>=8 -> zero regs)
        uint32_t a1h0, a1l0, a1h1, a1l1;
        {
            float2 f  = *(float2*)&Xw[g*8 + 2*t];
            float2 f8 = *(float2*)&Xw[(g+8)*8 + 2*t];
            split2(f.x,  f.y,  a1h0, a1l0);
            split2(f8.x, f8.y, a1h1, a1l1);
        }
        __syncwarp();   // reads done before next iteration's stores

        float bestdiff = 3.4e38f, bestP = 0.f;

        for (int e = 0; e < NENS; e++) {
            // ---- layer 1: X[16x16] @ W1[16x64]; split terms -> independent accs ----
            uint32_t A2h[4][4], A2l[4][4];
            const __nv_bfloat16* w1h = sW1hi + (e * HID) * W1K;
            const __nv_bfloat16* w1l = sW1lo + (e * HID) * W1K;
            #pragma unroll
            for (int nt = 0; nt < 8; nt++) {
                float cH0=0,cH1=0,cH2=0,cH3=0;
                float cM0=0,cM1=0,cM2=0,cM3=0;
                float cL0=0,cL1=0,cL2=0,cL3=0;
                int row = nt * 8 + g;
                uint32_t bh = *(const uint32_t*)(w1h + row * W1K + 2*t);
                uint32_t bl = *(const uint32_t*)(w1l + row * W1K + 2*t);
                mma16816(cH0,cH1,cH2,cH3, a1h0,a1h1, 0u,0u, bh, 0u);
                mma16816(cM0,cM1,cM2,cM3, a1h0,a1h1, 0u,0u, bl, 0u);
                mma16816(cL0,cL1,cL2,cL3, a1l0,a1l1, 0u,0u, bh, 0u);
                float2 bias = *(float2*)&sB1[e*HID + nt*8 + 2*t];
                float th0 = fast_tanh(cH0 + cM0 + cL0 + bias.x);
                float th1 = fast_tanh(cH1 + cM1 + cL1 + bias.y);
                float th2 = fast_tanh(cH2 + cM2 + cL2 + bias.x);
                float th3 = fast_tanh(cH3 + cM3 + cL3 + bias.y);
                // C->A remap: tile nt feeds A k-tile nt/2, regs (nt&1)*2, +1
                int kt = nt >> 1, hh = (nt & 1) * 2;
                split2(th0, th1, A2h[kt][hh],     A2l[kt][hh]);
                split2(th2, th3, A2h[kt][hh + 1], A2l[kt][hh + 1]);
            }

            // ---- layers 2+3: 3 independent mma chains per nt (len 4 each) ----
            float zp0 = 0.f, zp1 = 0.f;
            const __nv_bfloat16* w2h = sW2hi + (e * HID) * W2K;
            const __nv_bfloat16* w2l = sW2lo + (e * HID) * W2K;
            for (int nt = 0; nt < 8; nt++) {            // runtime loop (I-cache)
                float cH0=0,cH1=0,cH2=0,cH3=0;
                float cM0=0,cM1=0,cM2=0,cM3=0;
                float cL0=0,cL1=0,cL2=0,cL3=0;
                const __nv_bfloat16* rh  = w2h + (nt*8 + g) * W2K + 2*t;
                const __nv_bfloat16* rl2 = w2l + (nt*8 + g) * W2K + 2*t;
                #pragma unroll
                for (int kt = 0; kt < 4; kt++) {
                    uint32_t bh0 = *(const uint32_t*)(rh  + kt*16);
                    uint32_t bh1 = *(const uint32_t*)(rh  + kt*16 + 8);
                    uint32_t bl0 = *(const uint32_t*)(rl2 + kt*16);
                    uint32_t bl1 = *(const uint32_t*)(rl2 + kt*16 + 8);
                    mma16816(cH0,cH1,cH2,cH3, A2h[kt][0],A2h[kt][1],A2h[kt][2],A2h[kt][3], bh0,bh1);
                    mma16816(cM0,cM1,cM2,cM3, A2h[kt][0],A2h[kt][1],A2h[kt][2],A2h[kt][3], bl0,bl1);
                    mma16816(cL0,cL1,cL2,cL3, A2l[kt][0],A2l[kt][1],A2l[kt][2],A2l[kt][3], bh0,bh1);
                }
                float2 bias = *(float2*)&sB2[e*HID + nt*8 + 2*t];
                float2 wv   = *(float2*)&sW3[e*HID + nt*8 + 2*t];
                float th0 = fast_tanh(cH0 + cM0 + cL0 + bias.x);
                float th1 = fast_tanh(cH1 + cM1 + cL1 + bias.y);
                float th2 = fast_tanh(cH2 + cM2 + cL2 + bias.x);
                float th3 = fast_tanh(cH3 + cM3 + cL3 + bias.y);
                zp0 += th0 * wv.x + th1 * wv.y;
                zp1 += th2 * wv.x + th3 * wv.y;
            }
            // reduce over the 4 lanes of each row-group
            zp0 += __shfl_xor_sync(0xffffffffu, zp0, 1);
            zp0 += __shfl_xor_sync(0xffffffffu, zp0, 2);
            zp1 += __shfl_xor_sync(0xffffffffu, zp1, 1);
            zp1 += __shfl_xor_sync(0xffffffffu, zp1, 2);
            int src = (lane & 7) * 4;
            float za = __shfl_sync(0xffffffffu, zp0, src);
            float zb = __shfl_sync(0xffffffffu, zp1, src);

            if (lane < 16 && cell < N) {
                float z = ((lane < 8) ? za : zb) + sB3[e];
                float pc = aPress * (1.0f + 2.0f * fast_exp(z));
                float rC, hC, vsl, Vs1, vsr, Vs2;
                get_vel_shock(pc, rl, pl, vl, -1.0f, rC, hC, vsl, Vs1);
                get_vel_shock(pc, rr, pr, vr,  1.0f, rC, hC, vsr, Vs2);
                float d = fabsf(vsl - vsr);
                if (d < bestdiff) { bestdiff = d; bestP = pc; }
            }
        }

        if (lane < 16 && cell < N)
            finish_cell(F, out, cell, bestP, rl, pl, vl, rr, pr, vr);
    }
}

extern "C" void kernel_launch(void* const* d_in, const int* in_sizes, int n_in,
                              void* d_out, int out_size)
{
    const float* P  = (const float*)d_in[0];
    const float* F  = (const float*)d_in[2];
    const float* W1 = (const float*)d_in[5];
    const float* b1 = (const float*)d_in[6];
    const float* W2 = (const float*)d_in[7];
    const float* b2 = (const float*)d_in[8];
    const float* W3 = (const float*)d_in[9];
    const float* b3 = (const float*)d_in[10];
    float* out = (float*)d_out;
    const int N = in_sizes[0] / 6;

    const int nprep = NENS*HID*W1K + NENS*HID*W2K;
    prep_kernel<<<(nprep + 255) / 256, 256>>>(W1, W2);

    cudaFuncSetAttribute(solver_mma,
                         cudaFuncAttributeMaxDynamicSharedMemorySize, SMEM_BYTES);
    solver_mma<<<148, NTHREADS, SMEM_BYTES>>>(P, F, b1, b2, W3, b3, out, N);
}

// round 8
// speedup vs baseline: 1.8851x; 1.2194x over previous
#include <cuda_runtime.h>
#include <cuda_bf16.h>
#include <math.h>
#include <stdint.h>

#define NTHREADS 512
#define NWARPS   (NTHREADS/32)
#define NENS 8
#define HID 64

// packed weight records in __device__ scratch (allocation-free)
// W2: [e][nt(8)][kt(4)][lane(32)] uint4 {hi_b0, hi_b1, lo_b0, lo_b1}
// W1: [e][nt(8)][lane(32)]        uint2 {hi_b0, lo_b0}   (k>=8 rows are zero)
// BW: [e][nt(8)][t(4)]            float4 {b2.x, b2.y, w3.x, w3.y}
__device__ __align__(16) uint4  g_w2p[NENS * 8 * 4 * 32];   // 131072 B
__device__ __align__(16) uint2  g_w1p[NENS * 8 * 32];       // 16384 B
__device__ __align__(16) float4 g_bw [NENS * 8 * 4];        // 4096 B

// ---- shared memory byte offsets ----
#define SM_W2P 0
#define SM_W1P (SM_W2P + 131072)
#define SM_B1  (SM_W1P + 16384)            // 147456, 8*64 floats
#define SM_BW  (SM_B1 + NENS*HID*4)        // 149504
#define SM_B3  (SM_BW + 4096)              // 153600
#define SM_X   (SM_B3 + 32)                // 153632
#define SMEM_BYTES (SM_X + NWARPS*16*8*4)  // 161824

// ---- fast transcendentals ----
__device__ __forceinline__ float fast_tanh(float x) {
    float e, r;
    asm("ex2.approx.f32 %0, %1;" : "=f"(e) : "f"(x * 2.8853900817779268f));
    asm("rcp.approx.f32 %0, %1;" : "=f"(r) : "f"(e + 1.0f));
    return fmaf(-2.0f, r, 1.0f);
}
__device__ __forceinline__ float fast_exp(float x) {
    float e;
    asm("ex2.approx.f32 %0, %1;" : "=f"(e) : "f"(x * 1.4426950408889634f));
    return e;
}

// ---- bf16x2 pack + hi/lo split: v = hi + lo, err ~2^-18 ----
__device__ __forceinline__ void split2(float v0, float v1, uint32_t& hi, uint32_t& lo) {
    __nv_bfloat162 h = __floats2bfloat162_rn(v0, v1);
    hi = *reinterpret_cast<uint32_t*>(&h);
    float f0 = __uint_as_float(hi << 16);
    float f1 = __uint_as_float(hi & 0xffff0000u);
    __nv_bfloat162 l = __floats2bfloat162_rn(v0 - f0, v1 - f1);
    lo = *reinterpret_cast<uint32_t*>(&l);
}

// ---- mma.sync m16n8k16 bf16, fp32 accum ----
__device__ __forceinline__ void mma16816(float& c0, float& c1, float& c2, float& c3,
    uint32_t a0, uint32_t a1, uint32_t a2, uint32_t a3, uint32_t b0, uint32_t b1)
{
    asm volatile("mma.sync.aligned.m16n8k16.row.col.f32.bf16.bf16.f32 "
        "{%0,%1,%2,%3},{%4,%5,%6,%7},{%8,%9},{%0,%1,%2,%3};"
        : "+f"(c0), "+f"(c1), "+f"(c2), "+f"(c3)
        : "r"(a0), "r"(a1), "r"(a2), "r"(a3), "r"(b0), "r"(b1));
}

// Relativistic shock jump (Taub adiabat), gamma = 5/3.
__device__ __forceinline__ void get_vel_shock(
    float pC, float rho, float p, float v, float sign,
    float& rhoC, float& hC, float& vstar, float& Vs)
{
    float h  = 1.0f + 2.5f * p / rho;
    float W  = 1.0f / sqrtf(1.0f - v * v);
    float dp = p - pC;
    float A  = 1.0f + 0.4f * dp / pC;
    float B  = -0.4f * dp / pC;
    float C  = h * dp / rho - h * h;
    float disc = fmaxf(B * B - 4.0f * A * C, 0.0f);
    hC   = (-B + sqrtf(disc)) / (2.0f * A);
    rhoC = 2.5f * pC / (hC - 1.0f);
    float j2   = fmaxf((pC - p) / (h / rho - hC / rhoC), 1e-12f);
    float jabs = sqrtf(j2);
    float rw   = rho * W;
    float a2   = rw * rw;
    Vs = (a2 * v + sign * jabs * sqrtf(j2 + a2 * (1.0f - v * v))) / (a2 + j2);
    float Ws = 1.0f / sqrtf(fmaxf(1.0f - Vs * Vs, 1e-12f));
    float js = sign * jabs;
    vstar = (h * W * v + Ws * (pC - p) / js) /
            (h * W + (pC - p) * (Ws * v / js + 1.0f / (rho * W)));
}

// ---- prep: build packed fragment tables ----
__global__ void prep_kernel(const float* __restrict__ W1, const float* __restrict__ W2,
                            const float* __restrict__ b2, const float* __restrict__ W3)
{
    int idx = blockIdx.x * blockDim.x + threadIdx.x;
    if (idx < NENS*8*4*32) {                       // W2 packed
        int lane = idx & 31, kt = (idx >> 5) & 3, nt = (idx >> 7) & 7, e = idx >> 10;
        int gg = lane >> 2, t = lane & 3;
        int n = nt * 8 + gg;
        int kb = kt * 16 + 2 * t;
        float w00 = W2[(e*HID + kb    )*HID + n], w01 = W2[(e*HID + kb + 1)*HID + n];
        float w10 = W2[(e*HID + kb + 8)*HID + n], w11 = W2[(e*HID + kb + 9)*HID + n];
        uint32_t h0, l0, h1, l1;
        split2(w00, w01, h0, l0);
        split2(w10, w11, h1, l1);
        g_w2p[idx] = make_uint4(h0, h1, l0, l1);
    } else if (idx < NENS*8*4*32 + NENS*8*32) {    // W1 packed
        int j = idx - NENS*8*4*32;
        int lane = j & 31, nt = (j >> 5) & 7, e = j >> 8;
        int gg = lane >> 2, t = lane & 3;
        int n = nt * 8 + gg;
        int k = 2 * t;
        float w0 = (k     < 6) ? W1[(e*6 + k    )*HID + n] : 0.0f;
        float w1 = (k + 1 < 6) ? W1[(e*6 + k + 1)*HID + n] : 0.0f;
        uint32_t h0, l0;
        split2(w0, w1, h0, l0);
        g_w1p[j] = make_uint2(h0, l0);
    } else if (idx < NENS*8*4*32 + NENS*8*32 + NENS*8*4) {  // b2 + W3 packed
        int j = idx - NENS*8*4*32 - NENS*8*32;
        int t = j & 3, nt = (j >> 2) & 7, e = j >> 5;
        int base = e*HID + nt*8 + 2*t;
        g_bw[j] = make_float4(b2[base], b2[base+1], W3[base], W3[base+1]);
    }
}

__global__ void __launch_bounds__(NTHREADS)
solver_mma(const float* __restrict__ P, const float* __restrict__ F,
           const float* __restrict__ b1g, const float* __restrict__ b3g,
           float* __restrict__ out, int N)
{
    extern __shared__ char smem[];
    uint4*  sW2p = (uint4*)(smem + SM_W2P);
    uint2*  sW1p = (uint2*)(smem + SM_W1P);
    float*  sB1  = (float*)(smem + SM_B1);
    float4* sBW  = (float4*)(smem + SM_BW);
    float*  sB3  = (float*)(smem + SM_B3);
    float*  sX   = (float*)(smem + SM_X);

    // cooperative smem fill
    {
        const int4* s1 = (const int4*)g_w2p;  int4* d1 = (int4*)sW2p;
        for (int i = threadIdx.x; i < NENS*8*4*32; i += NTHREADS) d1[i] = s1[i];
        const int2* s2 = (const int2*)g_w1p;  int2* d2 = (int2*)sW1p;
        for (int i = threadIdx.x; i < NENS*8*32; i += NTHREADS) d2[i] = s2[i];
        const int4* s3 = (const int4*)g_bw;   int4* d3 = (int4*)sBW;
        for (int i = threadIdx.x; i < NENS*8*4; i += NTHREADS) d3[i] = s3[i];
        for (int i = threadIdx.x; i < NENS*HID; i += NTHREADS) sB1[i] = b1g[i];
        if (threadIdx.x < NENS) sB3[threadIdx.x] = b3g[threadIdx.x];
    }
    __syncthreads();

    const int lane = threadIdx.x & 31, wid = threadIdx.x >> 5;
    const int g = lane >> 2, t = lane & 3;
    const int side = lane >> 4;          // 0 = Left state, 1 = Right state
    const int c    = lane & 15;          // cell index within tile
    const float sgn = side ? 1.0f : -1.0f;
    const int ntiles = (N + 15) >> 4;
    float* Xw = sX + wid * 128;

    for (int tile = blockIdx.x * NWARPS + wid; tile < ntiles; tile += gridDim.x * NWARPS) {
        const int cell = tile * 16 + c;
        const bool act = (cell < N);

        // each lane owns ONE side of one cell
        float rho = 1.0f, p = 1.0f, v = 0.0f;
        if (act) {
            rho = P[cell*6 + side];
            p   = P[cell*6 + 2 + side];
            v   = P[cell*6 + 4 + side];
            Xw[c*8 + side]     = logf(rho);
            Xw[c*8 + 2 + side] = logf(p);
            Xw[c*8 + 4 + side] = v;
        } else {
            Xw[c*8 + side]     = 0.0f;
            Xw[c*8 + 2 + side] = 0.0f;
            Xw[c*8 + 4 + side] = 0.0f;
        }
        if (side == 0) { Xw[c*8 + 6] = 0.0f; Xw[c*8 + 7] = 0.0f; }
        __syncwarp();
        const float aPress = fmaxf(p, __shfl_xor_sync(0xffffffffu, p, 16));

        // layer1 A-fragments (rows = cells g, g+8; k = 2t,2t+1)
        uint32_t a1h0, a1l0, a1h1, a1l1;
        {
            float2 f  = *(float2*)&Xw[g*8 + 2*t];
            float2 f8 = *(float2*)&Xw[(g+8)*8 + 2*t];
            split2(f.x,  f.y,  a1h0, a1l0);
            split2(f8.x, f8.y, a1h1, a1l1);
        }
        __syncwarp();   // reads done before next iteration's stores

        float bestdiff = 3.4e38f, bestP = 0.0f;

        for (int e = 0; e < NENS; e++) {
            // ---- layer 1: X[16x16] @ W1[16x64] ----
            uint32_t A2h[4][4], A2l[4][4];
            const uint2*  w1p = sW1p + (e * 8) * 32 + lane;
            #pragma unroll
            for (int nt = 0; nt < 8; nt++) {
                float2 bias = *(float2*)&sB1[e*HID + nt*8 + 2*t];
                uint2 w = w1p[nt * 32];              // {hi_b0, lo_b0}
                float cH0=bias.x, cH1=bias.y, cH2=bias.x, cH3=bias.y;
                float cM0=0,cM1=0,cM2=0,cM3=0;
                float cL0=0,cL1=0,cL2=0,cL3=0;
                mma16816(cH0,cH1,cH2,cH3, a1h0,a1h1, 0u,0u, w.x, 0u);
                mma16816(cM0,cM1,cM2,cM3, a1h0,a1h1, 0u,0u, w.y, 0u);
                mma16816(cL0,cL1,cL2,cL3, a1l0,a1l1, 0u,0u, w.x, 0u);
                float th0 = fast_tanh(cH0 + cM0 + cL0);
                float th1 = fast_tanh(cH1 + cM1 + cL1);
                float th2 = fast_tanh(cH2 + cM2 + cL2);
                float th3 = fast_tanh(cH3 + cM3 + cL3);
                int kt = nt >> 1, hh = (nt & 1) * 2;   // C->A remap
                split2(th0, th1, A2h[kt][hh],     A2l[kt][hh]);
                split2(th2, th3, A2h[kt][hh + 1], A2l[kt][hh + 1]);
            }

            // ---- layers 2+3: packed B-frags, 1 LDS.128 per kt ----
            float zp0 = 0.0f, zp1 = 0.0f;
            const uint4* w2p = sW2p + (e * 8) * 4 * 32 + lane;
            for (int nt = 0; nt < 8; nt++) {           // runtime loop (I-cache)
                float4 bw = sBW[(e*8 + nt)*4 + t];     // {b2.x,b2.y,w3.x,w3.y}
                float cH0=bw.x, cH1=bw.y, cH2=bw.x, cH3=bw.y;
                float cM0=0,cM1=0,cM2=0,cM3=0;
                float cL0=0,cL1=0,cL2=0,cL3=0;
                const uint4* wrow = w2p + nt * (4*32);
                #pragma unroll
                for (int kt = 0; kt < 4; kt++) {
                    uint4 w = wrow[kt * 32];           // {hi_b0,hi_b1,lo_b0,lo_b1}
                    mma16816(cH0,cH1,cH2,cH3, A2h[kt][0],A2h[kt][1],A2h[kt][2],A2h[kt][3], w.x,w.y);
                    mma16816(cM0,cM1,cM2,cM3, A2h[kt][0],A2h[kt][1],A2h[kt][2],A2h[kt][3], w.z,w.w);
                    mma16816(cL0,cL1,cL2,cL3, A2l[kt][0],A2l[kt][1],A2l[kt][2],A2l[kt][3], w.x,w.y);
                }
                float th0 = fast_tanh(cH0 + cM0 + cL0);
                float th1 = fast_tanh(cH1 + cM1 + cL1);
                float th2 = fast_tanh(cH2 + cM2 + cL2);
                float th3 = fast_tanh(cH3 + cM3 + cL3);
                zp0 += th0 * bw.z + th1 * bw.w;
                zp1 += th2 * bw.z + th3 * bw.w;
            }
            // reduce over the 4 lanes of each row-group
            zp0 += __shfl_xor_sync(0xffffffffu, zp0, 1);
            zp0 += __shfl_xor_sync(0xffffffffu, zp0, 2);
            zp1 += __shfl_xor_sync(0xffffffffu, zp1, 1);
            zp1 += __shfl_xor_sync(0xffffffffu, zp1, 2);
            int src = (c & 7) * 4;
            float za = __shfl_sync(0xffffffffu, zp0, src);
            float zb = __shfl_sync(0xffffffffu, zp1, src);
            float z  = ((c < 8) ? za : zb) + sB3[e];

            // per-ensemble shock: one parallel get_vel_shock per lane (own side)
            float pc = aPress * (1.0f + 2.0f * fast_exp(z));
            float rC, hC, vs, Vs;
            get_vel_shock(pc, rho, p, v, sgn, rC, hC, vs, Vs);
            float vsO = __shfl_xor_sync(0xffffffffu, vs, 16);
            float d = fabsf(vs - vsO);        // symmetric: both lanes agree
            if (d < bestdiff) { bestdiff = d; bestP = pc; }
        }

        // final shock recompute, parallel over sides; exchange via shfl
        float rhoC, hC, vstar, vsh;
        get_vel_shock(bestP, rho, p, v, sgn, rhoC, hC, vstar, vsh);
        float vstarO = __shfl_xor_sync(0xffffffffu, vstar, 16);
        float vshO   = __shfl_xor_sync(0xffffffffu, vsh,   16);
        float rhoCO  = __shfl_xor_sync(0xffffffffu, rhoC,  16);
        float hCO    = __shfl_xor_sync(0xffffffffu, hC,    16);

        if (side == 0 && act) {
            // own = Left, other = Right
            float lam = 0.5f * (vstarO + vstar);
            float WC  = 1.0f / sqrtf(1.0f - lam * lam);
            float densCL = WC * rhoC, densCR = WC * rhoCO;

            float f0 = 0.0f, f1 = 0.0f, f2 = 0.0f;
            if (vsh >= 0.0f) { f0 = F[cell*6+0]; f1 = F[cell*6+2]; f2 = F[cell*6+4]; }
            if (vsh < 0.0f && lam > 0.0f) {
                f0 = densCL * lam;
                f1 = densCL * (WC * hC - 1.0f) * lam;
                f2 = (WC * WC * rhoC * hC * lam) * lam + bestP;
            }
            if (lam <= 0.0f && vshO > 0.0f) {
                f0 = densCR * lam;
                f1 = densCR * (WC * hCO - 1.0f) * lam;
                f2 = (WC * WC * rhoCO * hCO * lam) * lam + bestP;
            }
            if (vshO <= 0.0f) { f0 = F[cell*6+1]; f1 = F[cell*6+3]; f2 = F[cell*6+5]; }
            out[cell*3+0] = f0; out[cell*3+1] = f1; out[cell*3+2] = f2;
        }
    }
}

extern "C" void kernel_launch(void* const* d_in, const int* in_sizes, int n_in,
                              void* d_out, int out_size)
{
    const float* P  = (const float*)d_in[0];
    const float* F  = (const float*)d_in[2];
    const float* W1 = (const float*)d_in[5];
    const float* b1 = (const float*)d_in[6];
    const float* W2 = (const float*)d_in[7];
    const float* b2 = (const float*)d_in[8];
    const float* W3 = (const float*)d_in[9];
    const float* b3 = (const float*)d_in[10];
    float* out = (float*)d_out;
    const int N = in_sizes[0] / 6;

    const int nprep = NENS*8*4*32 + NENS*8*32 + NENS*8*4;
    prep_kernel<<<(nprep + 255) / 256, 256>>>(W1, W2, b2, W3);

    cudaFuncSetAttribute(solver_mma,
                         cudaFuncAttributeMaxDynamicSharedMemorySize, SMEM_BYTES);
    solver_mma<<<148, NTHREADS, SMEM_BYTES>>>(P, F, b1, b3, out, N);
}

// round 9
// speedup vs baseline: 2.1849x; 1.1590x over previous
#include <cuda_runtime.h>
#include <cuda_bf16.h>
#include <math.h>
#include <stdint.h>

#define NTHREADS 512
#define NWARPS   (NTHREADS/32)
#define NENS 8
#define HID 64

#define TANH_C  2.8853900817779268f   // 2*log2(e) folded into W1,b1,W2,b2
#define LOG2E   1.4426950408889634f   // folded into W3,b3
#define LN2     0.6931471805599453f

// packed weight records in __device__ scratch (allocation-free)
// W2: [e][nt(8)][kt(4)][lane(32)] uint4 {hi_b0, hi_b1, lo_b0, lo_b1}  (pre-scaled by TANH_C)
// W1: [e][nt(8)][lane(32)]        uint2 {hi_b0, lo_b0}                (pre-scaled by TANH_C)
// BW: [e][nt(8)][t(4)]            float4 {b2.x*C, b2.y*C, w3.x*log2e, w3.y*log2e}
__device__ __align__(16) uint4  g_w2p[NENS * 8 * 4 * 32];   // 131072 B
__device__ __align__(16) uint2  g_w1p[NENS * 8 * 32];       // 16384 B
__device__ __align__(16) float4 g_bw [NENS * 8 * 4];        // 4096 B

// ---- shared memory byte offsets ----
#define SM_W2P 0
#define SM_W1P (SM_W2P + 131072)
#define SM_B1  (SM_W1P + 16384)            // 147456, 8*64 floats
#define SM_BW  (SM_B1 + NENS*HID*4)        // 149504
#define SM_B3  (SM_BW + 4096)              // 153600
#define SM_X   (SM_B3 + 32)                // 153632
#define SMEM_BYTES (SM_X + NWARPS*16*8*4)  // 161824

// ---- MUFU approx primitives (rel err ~2^-22, far below 3.5e-5 noise floor) ----
__device__ __forceinline__ float fast_rcp(float x) {
    float r; asm("rcp.approx.f32 %0, %1;" : "=f"(r) : "f"(x)); return r;
}
__device__ __forceinline__ float fast_rsqrt(float x) {
    float r; asm("rsqrt.approx.f32 %0, %1;" : "=f"(r) : "f"(x)); return r;
}
__device__ __forceinline__ float fast_sqrt(float x) {
    float r; asm("sqrt.approx.f32 %0, %1;" : "=f"(r) : "f"(x)); return r;
}
__device__ __forceinline__ float fast_log(float x) {
    float l; asm("lg2.approx.f32 %0, %1;" : "=f"(l) : "f"(x)); return l * LN2;
}
// input pre-scaled by 2*log2(e): tanh = 1 - 2/(ex2(s)+1)
__device__ __forceinline__ float fast_tanh_pre(float s) {
    float e, r;
    asm("ex2.approx.f32 %0, %1;" : "=f"(e) : "f"(s));
    asm("rcp.approx.f32 %0, %1;" : "=f"(r) : "f"(e + 1.0f));
    return fmaf(-2.0f, r, 1.0f);
}
// input pre-scaled by log2(e): exp = ex2(z)
__device__ __forceinline__ float fast_exp_pre(float z) {
    float e; asm("ex2.approx.f32 %0, %1;" : "=f"(e) : "f"(z)); return e;
}

// ---- bf16x2 pack + hi/lo split: v = hi + lo, err ~2^-18 ----
__device__ __forceinline__ void split2(float v0, float v1, uint32_t& hi, uint32_t& lo) {
    __nv_bfloat162 h = __floats2bfloat162_rn(v0, v1);
    hi = *reinterpret_cast<uint32_t*>(&h);
    float f0 = __uint_as_float(hi << 16);
    float f1 = __uint_as_float(hi & 0xffff0000u);
    __nv_bfloat162 l = __floats2bfloat162_rn(v0 - f0, v1 - f1);
    lo = *reinterpret_cast<uint32_t*>(&l);
}

// ---- mma.sync m16n8k16 bf16, fp32 accum ----
__device__ __forceinline__ void mma16816(float& c0, float& c1, float& c2, float& c3,
    uint32_t a0, uint32_t a1, uint32_t a2, uint32_t a3, uint32_t b0, uint32_t b1)
{
    asm volatile("mma.sync.aligned.m16n8k16.row.col.f32.bf16.bf16.f32 "
        "{%0,%1,%2,%3},{%4,%5,%6,%7},{%8,%9},{%0,%1,%2,%3};"
        : "+f"(c0), "+f"(c1), "+f"(c2), "+f"(c3)
        : "r"(a0), "r"(a1), "r"(a2), "r"(a3), "r"(b0), "r"(b1));
}

// Relativistic shock jump (Taub adiabat), gamma = 5/3.  Division-free (MUFU approx).
__device__ __forceinline__ void get_vel_shock(
    float pC, float rho, float p, float v, float sign,
    float& rhoC, float& hC, float& vstar, float& Vs)
{
    float rrho = fast_rcp(rho);
    float h    = fmaf(2.5f * p, rrho, 1.0f);
    float omv2 = 1.0f - v * v;
    float W    = fast_rsqrt(omv2);
    float dp   = p - pC;
    float rpC  = fast_rcp(pC);
    float t04  = 0.4f * dp * rpC;
    float A    = 1.0f + t04;
    float B    = -t04;
    float C    = h * dp * rrho - h * h;
    float disc = fmaxf(fmaf(B, B, -4.0f * A * C), 0.0f);
    hC   = (fast_sqrt(disc) - B) * (0.5f * fast_rcp(A));
    float hCm1 = hC - 1.0f;
    rhoC = 2.5f * pC * fast_rcp(hCm1);
    // h/rho - hC/rhoC;  hC/rhoC = 0.4 * hC * (hC-1) / pC
    float denj = h * rrho - 0.4f * hC * hCm1 * rpC;
    float j2   = fmaxf((pC - p) * fast_rcp(denj), 1e-12f);
    float jabs = fast_sqrt(j2);
    float rw   = rho * W;
    float a2   = rw * rw;
    Vs = (a2 * v + sign * jabs * fast_sqrt(fmaf(a2, omv2, j2))) * fast_rcp(a2 + j2);
    float Ws = fast_rsqrt(fmaxf(1.0f - Vs * Vs, 1e-12f));
    float js = sign * jabs;
    float rjs = fast_rcp(js);
    float hW  = h * W;
    float num = hW * v + Ws * (pC - p) * rjs;
    // 1/(rho*W) = rrho * sqrt(omv2) = rrho * omv2 * W
    float den = hW + (pC - p) * (Ws * v * rjs + rrho * omv2 * W);
    vstar = num * fast_rcp(den);
}

// ---- prep: build packed fragment tables (scales folded in) ----
__global__ void prep_kernel(const float* __restrict__ W1, const float* __restrict__ W2,
                            const float* __restrict__ b2, const float* __restrict__ W3)
{
    int idx = blockIdx.x * blockDim.x + threadIdx.x;
    if (idx < NENS*8*4*32) {                       // W2 packed (scaled by TANH_C)
        int lane = idx & 31, kt = (idx >> 5) & 3, nt = (idx >> 7) & 7, e = idx >> 10;
        int gg = lane >> 2, t = lane & 3;
        int n = nt * 8 + gg;
        int kb = kt * 16 + 2 * t;
        float w00 = TANH_C * W2[(e*HID + kb    )*HID + n];
        float w01 = TANH_C * W2[(e*HID + kb + 1)*HID + n];
        float w10 = TANH_C * W2[(e*HID + kb + 8)*HID + n];
        float w11 = TANH_C * W2[(e*HID + kb + 9)*HID + n];
        uint32_t h0, l0, h1, l1;
        split2(w00, w01, h0, l0);
        split2(w10, w11, h1, l1);
        g_w2p[idx] = make_uint4(h0, h1, l0, l1);
    } else if (idx < NENS*8*4*32 + NENS*8*32) {    // W1 packed (scaled by TANH_C)
        int j = idx - NENS*8*4*32;
        int lane = j & 31, nt = (j >> 5) & 7, e = j >> 8;
        int gg = lane >> 2, t = lane & 3;
        int n = nt * 8 + gg;
        int k = 2 * t;
        float w0 = (k     < 6) ? TANH_C * W1[(e*6 + k    )*HID + n] : 0.0f;
        float w1 = (k + 1 < 6) ? TANH_C * W1[(e*6 + k + 1)*HID + n] : 0.0f;
        uint32_t h0, l0;
        split2(w0, w1, h0, l0);
        g_w1p[j] = make_uint2(h0, l0);
    } else if (idx < NENS*8*4*32 + NENS*8*32 + NENS*8*4) {  // b2*TANH_C + W3*LOG2E
        int j = idx - NENS*8*4*32 - NENS*8*32;
        int t = j & 3, nt = (j >> 2) & 7, e = j >> 5;
        int base = e*HID + nt*8 + 2*t;
        g_bw[j] = make_float4(TANH_C * b2[base], TANH_C * b2[base+1],
                              LOG2E  * W3[base], LOG2E  * W3[base+1]);
    }
}

__global__ void __launch_bounds__(NTHREADS)
solver_mma(const float* __restrict__ P, const float* __restrict__ F,
           const float* __restrict__ b1g, const float* __restrict__ b3g,
           float* __restrict__ out, int N)
{
    extern __shared__ char smem[];
    uint4*  sW2p = (uint4*)(smem + SM_W2P);
    uint2*  sW1p = (uint2*)(smem + SM_W1P);
    float*  sB1  = (float*)(smem + SM_B1);
    float4* sBW  = (float4*)(smem + SM_BW);
    float*  sB3  = (float*)(smem + SM_B3);
    float*  sX   = (float*)(smem + SM_X);

    // cooperative smem fill (b1 scaled by TANH_C, b3 by LOG2E here)
    {
        const int4* s1 = (const int4*)g_w2p;  int4* d1 = (int4*)sW2p;
        for (int i = threadIdx.x; i < NENS*8*4*32; i += NTHREADS) d1[i] = s1[i];
        const int2* s2 = (const int2*)g_w1p;  int2* d2 = (int2*)sW1p;
        for (int i = threadIdx.x; i < NENS*8*32; i += NTHREADS) d2[i] = s2[i];
        const int4* s3 = (const int4*)g_bw;   int4* d3 = (int4*)sBW;
        for (int i = threadIdx.x; i < NENS*8*4; i += NTHREADS) d3[i] = s3[i];
        for (int i = threadIdx.x; i < NENS*HID; i += NTHREADS) sB1[i] = TANH_C * b1g[i];
        if (threadIdx.x < NENS) sB3[threadIdx.x] = LOG2E * b3g[threadIdx.x];
    }
    __syncthreads();

    const int lane = threadIdx.x & 31, wid = threadIdx.x >> 5;
    const int g = lane >> 2, t = lane & 3;
    const int side = lane >> 4;          // 0 = Left state, 1 = Right state
    const int c    = lane & 15;          // cell index within tile
    const float sgn = side ? 1.0f : -1.0f;
    const int ntiles = (N + 15) >> 4;
    float* Xw = sX + wid * 128;

    for (int tile = blockIdx.x * NWARPS + wid; tile < ntiles; tile += gridDim.x * NWARPS) {
        const int cell = tile * 16 + c;
        const bool act = (cell < N);

        // each lane owns ONE side of one cell
        float rho = 1.0f, p = 1.0f, v = 0.0f;
        if (act) {
            rho = P[cell*6 + side];
            p   = P[cell*6 + 2 + side];
            v   = P[cell*6 + 4 + side];
            Xw[c*8 + side]     = fast_log(rho);
            Xw[c*8 + 2 + side] = fast_log(p);
            Xw[c*8 + 4 + side] = v;
        } else {
            Xw[c*8 + side]     = 0.0f;
            Xw[c*8 + 2 + side] = 0.0f;
            Xw[c*8 + 4 + side] = 0.0f;
        }
        if (side == 0) { Xw[c*8 + 6] = 0.0f; Xw[c*8 + 7] = 0.0f; }
        __syncwarp();
        const float aPress = fmaxf(p, __shfl_xor_sync(0xffffffffu, p, 16));

        // layer1 A-fragments (rows = cells g, g+8; k = 2t,2t+1)
        uint32_t a1h0, a1l0, a1h1, a1l1;
        {
            float2 f  = *(float2*)&Xw[g*8 + 2*t];
            float2 f8 = *(float2*)&Xw[(g+8)*8 + 2*t];
            split2(f.x,  f.y,  a1h0, a1l0);
            split2(f8.x, f8.y, a1h1, a1l1);
        }
        __syncwarp();   // reads done before next iteration's stores

        float bestdiff = 3.4e38f, bestP = 0.0f;

        for (int e = 0; e < NENS; e++) {
            // ---- layer 1: X[16x16] @ W1[16x64] (cross terms chained) ----
            uint32_t A2h[4][4], A2l[4][4];
            const uint2* w1p = sW1p + (e * 8) * 32 + lane;
            #pragma unroll
            for (int nt = 0; nt < 8; nt++) {
                float2 bias = *(float2*)&sB1[e*HID + nt*8 + 2*t];
                uint2 w = w1p[nt * 32];              // {hi_b0, lo_b0}
                float cH0=bias.x, cH1=bias.y, cH2=bias.x, cH3=bias.y;
                float cM0=0,cM1=0,cM2=0,cM3=0;
                mma16816(cH0,cH1,cH2,cH3, a1h0,a1h1, 0u,0u, w.x, 0u);
                mma16816(cM0,cM1,cM2,cM3, a1h0,a1h1, 0u,0u, w.y, 0u);
                mma16816(cM0,cM1,cM2,cM3, a1l0,a1l1, 0u,0u, w.x, 0u);  // chained
                float th0 = fast_tanh_pre(cH0 + cM0);
                float th1 = fast_tanh_pre(cH1 + cM1);
                float th2 = fast_tanh_pre(cH2 + cM2);
                float th3 = fast_tanh_pre(cH3 + cM3);
                int kt = nt >> 1, hh = (nt & 1) * 2;   // C->A remap
                split2(th0, th1, A2h[kt][hh],     A2l[kt][hh]);
                split2(th2, th3, A2h[kt][hh + 1], A2l[kt][hh + 1]);
            }

            // ---- layers 2+3: packed B-frags, 1 LDS.128 per kt ----
            float zp0 = 0.0f, zp1 = 0.0f;
            const uint4* w2p = sW2p + (e * 8) * 4 * 32 + lane;
            for (int nt = 0; nt < 8; nt++) {           // runtime loop (I-cache)
                float4 bw = sBW[(e*8 + nt)*4 + t];     // {b2.x,b2.y,w3.x,w3.y} (scaled)
                float cH0=bw.x, cH1=bw.y, cH2=bw.x, cH3=bw.y;
                float cM0=0,cM1=0,cM2=0,cM3=0;
                float cL0=0,cL1=0,cL2=0,cL3=0;
                const uint4* wrow = w2p + nt * (4*32);
                #pragma unroll
                for (int kt = 0; kt < 4; kt++) {
                    uint4 w = wrow[kt * 32];           // {hi_b0,hi_b1,lo_b0,lo_b1}
                    mma16816(cH0,cH1,cH2,cH3, A2h[kt][0],A2h[kt][1],A2h[kt][2],A2h[kt][3], w.x,w.y);
                    mma16816(cM0,cM1,cM2,cM3, A2h[kt][0],A2h[kt][1],A2h[kt][2],A2h[kt][3], w.z,w.w);
                    mma16816(cL0,cL1,cL2,cL3, A2l[kt][0],A2l[kt][1],A2l[kt][2],A2l[kt][3], w.x,w.y);
                }
                float th0 = fast_tanh_pre(cH0 + cM0 + cL0);
                float th1 = fast_tanh_pre(cH1 + cM1 + cL1);
                float th2 = fast_tanh_pre(cH2 + cM2 + cL2);
                float th3 = fast_tanh_pre(cH3 + cM3 + cL3);
                zp0 += th0 * bw.z + th1 * bw.w;
                zp1 += th2 * bw.z + th3 * bw.w;
            }
            // reduce over the 4 lanes of each row-group
            zp0 += __shfl_xor_sync(0xffffffffu, zp0, 1);
            zp0 += __shfl_xor_sync(0xffffffffu, zp0, 2);
            zp1 += __shfl_xor_sync(0xffffffffu, zp1, 1);
            zp1 += __shfl_xor_sync(0xffffffffu, zp1, 2);
            int src = (c & 7) * 4;
            float za = __shfl_sync(0xffffffffu, zp0, src);
            float zb = __shfl_sync(0xffffffffu, zp1, src);
            float z  = ((c < 8) ? za : zb) + sB3[e];   // z is log2e-scaled

            // per-ensemble shock: one parallel get_vel_shock per lane (own side)
            float pc = aPress * fmaf(2.0f, fast_exp_pre(z), 1.0f);
            float rC, hC, vs, Vs;
            get_vel_shock(pc, rho, p, v, sgn, rC, hC, vs, Vs);
            float vsO = __shfl_xor_sync(0xffffffffu, vs, 16);
            float d = fabsf(vs - vsO);        // symmetric: both lanes agree
            if (d < bestdiff) { bestdiff = d; bestP = pc; }
        }

        // final shock recompute, parallel over sides; exchange via shfl
        float rhoC, hC, vstar, vsh;
        get_vel_shock(bestP, rho, p, v, sgn, rhoC, hC, vstar, vsh);
        float vstarO = __shfl_xor_sync(0xffffffffu, vstar, 16);
        float vshO   = __shfl_xor_sync(0xffffffffu, vsh,   16);
        float rhoCO  = __shfl_xor_sync(0xffffffffu, rhoC,  16);
        float hCO    = __shfl_xor_sync(0xffffffffu, hC,    16);

        if (side == 0 && act) {
            // own = Left, other = Right
            float lam = 0.5f * (vstarO + vstar);
            float WC  = fast_rsqrt(1.0f - lam * lam);
            float densCL = WC * rhoC, densCR = WC * rhoCO;

            float f0 = 0.0f, f1 = 0.0f, f2 = 0.0f;
            if (vsh >= 0.0f) { f0 = F[cell*6+0]; f1 = F[cell*6+2]; f2 = F[cell*6+4]; }
            if (vsh < 0.0f && lam > 0.0f) {
                f0 = densCL * lam;
                f1 = densCL * (WC * hC - 1.0f) * lam;
                f2 = (WC * WC * rhoC * hC * lam) * lam + bestP;
            }
            if (lam <= 0.0f && vshO > 0.0f) {
                f0 = densCR * lam;
                f1 = densCR * (WC * hCO - 1.0f) * lam;
                f2 = (WC * WC * rhoCO * hCO * lam) * lam + bestP;
            }
            if (vshO <= 0.0f) { f0 = F[cell*6+1]; f1 = F[cell*6+3]; f2 = F[cell*6+5]; }
            out[cell*3+0] = f0; out[cell*3+1] = f1; out[cell*3+2] = f2;
        }
    }
}

extern "C" void kernel_launch(void* const* d_in, const int* in_sizes, int n_in,
                              void* d_out, int out_size)
{
    const float* P  = (const float*)d_in[0];
    const float* F  = (const float*)d_in[2];
    const float* W1 = (const float*)d_in[5];
    const float* b1 = (const float*)d_in[6];
    const float* W2 = (const float*)d_in[7];
    const float* b2 = (const float*)d_in[8];
    const float* W3 = (const float*)d_in[9];
    const float* b3 = (const float*)d_in[10];
    float* out = (float*)d_out;
    const int N = in_sizes[0] / 6;

    const int nprep = NENS*8*4*32 + NENS*8*32 + NENS*8*4;
    prep_kernel<<<(nprep + 255) / 256, 256>>>(W1, W2, b2, W3);

    cudaFuncSetAttribute(solver_mma,
                         cudaFuncAttributeMaxDynamicSharedMemorySize, SMEM_BYTES);
    solver_mma<<<148, NTHREADS, SMEM_BYTES>>>(P, F, b1, b3, out, N);
}

// round 10
// speedup vs baseline: 2.3463x; 1.0739x over previous
#include <cuda_runtime.h>
#include <cuda_bf16.h>
#include <math.h>
#include <stdint.h>

#define NTHREADS 640
#define NWARPS   (NTHREADS/32)
#define NENS 8
#define HID 64

#define TANH_C  2.8853900817779268f   // 2*log2(e) folded into W1,b1,W2,b2
#define LOG2E   1.4426950408889634f   // folded into W3,b3
#define LN2     0.6931471805599453f

// packed weight records in __device__ scratch (allocation-free)
// W2: [e][nt(8)][kt(4)][lane(32)] uint4 {hi_b0, hi_b1, lo_b0, lo_b1}   (pre-scaled by TANH_C)
// W1: [e][nt(8)][lane(32)]        uint4 {hi_b0, lo_b0, bias0, bias1}   (pre-scaled by TANH_C)
// BW: [e][nt(8)][t(4)]            float4 {b2.x*C, b2.y*C, -2*log2e*w3.x, -2*log2e*w3.y}
// B3: [e]                        log2e*(b3 + sum_j w3_j)
__device__ __align__(16) uint4  g_w2p[NENS * 8 * 4 * 32];   // 131072 B
__device__ __align__(16) uint4  g_w1p[NENS * 8 * 32];       // 32768 B
__device__ __align__(16) float4 g_bw [NENS * 8 * 4];        // 4096 B
__device__ float g_b3s[NENS];

// ---- shared memory byte offsets ----
#define SM_W2P 0
#define SM_W1P (SM_W2P + 131072)
#define SM_BW  (SM_W1P + 32768)            // 163840
#define SM_B3  (SM_BW + 4096)              // 167936
#define SM_X   (SM_B3 + 32)                // 167968
#define SMEM_BYTES (SM_X + NWARPS*16*8*4)  // 178208

// ---- MUFU approx primitives (rel err ~2^-22) ----
__device__ __forceinline__ float fast_rcp(float x) {
    float r; asm("rcp.approx.f32 %0, %1;" : "=f"(r) : "f"(x)); return r;
}
__device__ __forceinline__ float fast_rsqrt(float x) {
    float r; asm("rsqrt.approx.f32 %0, %1;" : "=f"(r) : "f"(x)); return r;
}
__device__ __forceinline__ float fast_sqrt(float x) {
    float r; asm("sqrt.approx.f32 %0, %1;" : "=f"(r) : "f"(x)); return r;
}
__device__ __forceinline__ float fast_log(float x) {
    float l; asm("lg2.approx.f32 %0, %1;" : "=f"(l) : "f"(x)); return l * LN2;
}
// input pre-scaled by 2*log2(e): tanh = 1 - 2/(ex2(s)+1)
__device__ __forceinline__ float fast_tanh_pre(float s) {
    float e, r;
    asm("ex2.approx.f32 %0, %1;" : "=f"(e) : "f"(s));
    asm("rcp.approx.f32 %0, %1;" : "=f"(r) : "f"(e + 1.0f));
    return fmaf(-2.0f, r, 1.0f);
}
// sigma-like: r = 1/(ex2(s)+1); caller folds (1-2r) algebra into weights
__device__ __forceinline__ float fast_r_pre(float s) {
    float e, r;
    asm("ex2.approx.f32 %0, %1;" : "=f"(e) : "f"(s));
    asm("rcp.approx.f32 %0, %1;" : "=f"(r) : "f"(e + 1.0f));
    return r;
}
__device__ __forceinline__ float fast_exp_pre(float z) {
    float e; asm("ex2.approx.f32 %0, %1;" : "=f"(e) : "f"(z)); return e;
}

// ---- bf16x2 pack + hi/lo split: v = hi + lo, err ~2^-18 ----
__device__ __forceinline__ void split2(float v0, float v1, uint32_t& hi, uint32_t& lo) {
    __nv_bfloat162 h = __floats2bfloat162_rn(v0, v1);
    hi = *reinterpret_cast<uint32_t*>(&h);
    float f0 = __uint_as_float(hi << 16);
    float f1 = __uint_as_float(hi & 0xffff0000u);
    __nv_bfloat162 l = __floats2bfloat162_rn(v0 - f0, v1 - f1);
    lo = *reinterpret_cast<uint32_t*>(&l);
}

// ---- mma.sync m16n8k16 / m16n8k8, bf16, fp32 accum ----
__device__ __forceinline__ void mma16816(float& c0, float& c1, float& c2, float& c3,
    uint32_t a0, uint32_t a1, uint32_t a2, uint32_t a3, uint32_t b0, uint32_t b1)
{
    asm volatile("mma.sync.aligned.m16n8k16.row.col.f32.bf16.bf16.f32 "
        "{%0,%1,%2,%3},{%4,%5,%6,%7},{%8,%9},{%0,%1,%2,%3};"
        : "+f"(c0), "+f"(c1), "+f"(c2), "+f"(c3)
        : "r"(a0), "r"(a1), "r"(a2), "r"(a3), "r"(b0), "r"(b1));
}
__device__ __forceinline__ void mma16808(float& c0, float& c1, float& c2, float& c3,
    uint32_t a0, uint32_t a1, uint32_t b0)
{
    asm volatile("mma.sync.aligned.m16n8k8.row.col.f32.bf16.bf16.f32 "
        "{%0,%1,%2,%3},{%4,%5},{%6},{%0,%1,%2,%3};"
        : "+f"(c0), "+f"(c1), "+f"(c2), "+f"(c3)
        : "r"(a0), "r"(a1), "r"(b0));
}

// Relativistic shock jump (Taub adiabat), gamma = 5/3.  Division-free (MUFU approx).
__device__ __forceinline__ void get_vel_shock(
    float pC, float rho, float p, float v, float sign,
    float& rhoC, float& hC, float& vstar, float& Vs)
{
    float rrho = fast_rcp(rho);
    float h    = fmaf(2.5f * p, rrho, 1.0f);
    float omv2 = 1.0f - v * v;
    float W    = fast_rsqrt(omv2);
    float dp   = p - pC;
    float rpC  = fast_rcp(pC);
    float t04  = 0.4f * dp * rpC;
    float A    = 1.0f + t04;
    float B    = -t04;
    float C    = h * dp * rrho - h * h;
    float disc = fmaxf(fmaf(B, B, -4.0f * A * C), 0.0f);
    hC   = (fast_sqrt(disc) - B) * (0.5f * fast_rcp(A));
    float hCm1 = hC - 1.0f;
    rhoC = 2.5f * pC * fast_rcp(hCm1);
    float denj = h * rrho - 0.4f * hC * hCm1 * rpC;
    float j2   = fmaxf((pC - p) * fast_rcp(denj), 1e-12f);
    float jabs = fast_sqrt(j2);
    float rw   = rho * W;
    float a2   = rw * rw;
    Vs = (a2 * v + sign * jabs * fast_sqrt(fmaf(a2, omv2, j2))) * fast_rcp(a2 + j2);
    float Ws = fast_rsqrt(fmaxf(1.0f - Vs * Vs, 1e-12f));
    float js = sign * jabs;
    float rjs = fast_rcp(js);
    float hW  = h * W;
    float num = hW * v + Ws * (pC - p) * rjs;
    float den = hW + (pC - p) * (Ws * v * rjs + rrho * omv2 * W);
    vstar = num * fast_rcp(den);
}

// ---- prep: build packed fragment tables (all scales folded in) ----
__global__ void prep_kernel(const float* __restrict__ W1, const float* __restrict__ W2,
                            const float* __restrict__ b1, const float* __restrict__ b2,
                            const float* __restrict__ W3, const float* __restrict__ b3)
{
    const int nW2 = NENS*8*4*32, nW1 = NENS*8*32, nBW = NENS*8*4;
    int idx = blockIdx.x * blockDim.x + threadIdx.x;
    if (idx < nW2) {                               // W2 packed (scaled by TANH_C)
        int lane = idx & 31, kt = (idx >> 5) & 3, nt = (idx >> 7) & 7, e = idx >> 10;
        int gg = lane >> 2, t = lane & 3;
        int n = nt * 8 + gg;
        int kb = kt * 16 + 2 * t;
        float w00 = TANH_C * W2[(e*HID + kb    )*HID + n];
        float w01 = TANH_C * W2[(e*HID + kb + 1)*HID + n];
        float w10 = TANH_C * W2[(e*HID + kb + 8)*HID + n];
        float w11 = TANH_C * W2[(e*HID + kb + 9)*HID + n];
        uint32_t h0, l0, h1, l1;
        split2(w00, w01, h0, l0);
        split2(w10, w11, h1, l1);
        g_w2p[idx] = make_uint4(h0, h1, l0, l1);
    } else if (idx < nW2 + nW1) {                  // W1 packed + bias (scaled)
        int j = idx - nW2;
        int lane = j & 31, nt = (j >> 5) & 7, e = j >> 8;
        int gg = lane >> 2, t = lane & 3;
        int n = nt * 8 + gg;
        int k = 2 * t;
        float w0 = (k     < 6) ? TANH_C * W1[(e*6 + k    )*HID + n] : 0.0f;
        float w1 = (k + 1 < 6) ? TANH_C * W1[(e*6 + k + 1)*HID + n] : 0.0f;
        uint32_t h0, l0;
        split2(w0, w1, h0, l0);
        float bias0 = TANH_C * b1[e*HID + nt*8 + 2*t];
        float bias1 = TANH_C * b1[e*HID + nt*8 + 2*t + 1];
        g_w1p[j] = make_uint4(h0, l0, __float_as_uint(bias0), __float_as_uint(bias1));
    } else if (idx < nW2 + nW1 + nBW) {            // b2*TANH_C + (-2*LOG2E)*W3
        int j = idx - nW2 - nW1;
        int t = j & 3, nt = (j >> 2) & 7, e = j >> 5;
        int base = e*HID + nt*8 + 2*t;
        g_bw[j] = make_float4(TANH_C * b2[base], TANH_C * b2[base+1],
                              -2.0f * LOG2E * W3[base], -2.0f * LOG2E * W3[base+1]);
    } else if (idx < nW2 + nW1 + nBW + NENS) {     // b3' = log2e*(b3 + sum w3)
        int e = idx - nW2 - nW1 - nBW;
        float s = b3[e];
        for (int j = 0; j < HID; j++) s += W3[e*HID + j];
        g_b3s[e] = LOG2E * s;
    }
}

__global__ void __launch_bounds__(NTHREADS, 1)
solver_mma(const float* __restrict__ P, const float* __restrict__ F,
           float* __restrict__ out, int N)
{
    extern __shared__ char smem[];
    uint4*  sW2p = (uint4*)(smem + SM_W2P);
    uint4*  sW1p = (uint4*)(smem + SM_W1P);
    float4* sBW  = (float4*)(smem + SM_BW);
    float*  sB3  = (float*)(smem + SM_B3);
    float*  sX   = (float*)(smem + SM_X);

    // cooperative smem fill
    {
        const int4* s1 = (const int4*)g_w2p;  int4* d1 = (int4*)sW2p;
        for (int i = threadIdx.x; i < NENS*8*4*32; i += NTHREADS) d1[i] = s1[i];
        const int4* s2 = (const int4*)g_w1p;  int4* d2 = (int4*)sW1p;
        for (int i = threadIdx.x; i < NENS*8*32; i += NTHREADS) d2[i] = s2[i];
        const int4* s3 = (const int4*)g_bw;   int4* d3 = (int4*)sBW;
        for (int i = threadIdx.x; i < NENS*8*4; i += NTHREADS) d3[i] = s3[i];
        if (threadIdx.x < NENS) sB3[threadIdx.x] = g_b3s[threadIdx.x];
    }
    __syncthreads();

    const int lane = threadIdx.x & 31, wid = threadIdx.x >> 5;
    const int g = lane >> 2, t = lane & 3;
    const int side = lane >> 4;          // 0 = Left state, 1 = Right state
    const int c    = lane & 15;          // cell index within tile
    const float sgn = side ? 1.0f : -1.0f;
    const int ntiles = (N + 15) >> 4;
    float* Xw = sX + wid * 128;

    for (int tile = blockIdx.x * NWARPS + wid; tile < ntiles; tile += gridDim.x * NWARPS) {
        const int cell = tile * 16 + c;
        const bool act = (cell < N);

        // each lane owns ONE side of one cell
        float rho = 1.0f, p = 1.0f, v = 0.0f;
        if (act) {
            rho = P[cell*6 + side];
            p   = P[cell*6 + 2 + side];
            v   = P[cell*6 + 4 + side];
            Xw[c*8 + side]     = fast_log(rho);
            Xw[c*8 + 2 + side] = fast_log(p);
            Xw[c*8 + 4 + side] = v;
        } else {
            Xw[c*8 + side]     = 0.0f;
            Xw[c*8 + 2 + side] = 0.0f;
            Xw[c*8 + 4 + side] = 0.0f;
        }
        if (side == 0) { Xw[c*8 + 6] = 0.0f; Xw[c*8 + 7] = 0.0f; }
        __syncwarp();
        const float aPress = fmaxf(p, __shfl_xor_sync(0xffffffffu, p, 16));

        // layer1 A-fragments (rows = cells g, g+8; k = 2t,2t+1), k8 layout
        uint32_t a1h0, a1l0, a1h1, a1l1;
        {
            float2 f  = *(float2*)&Xw[g*8 + 2*t];
            float2 f8 = *(float2*)&Xw[(g+8)*8 + 2*t];
            split2(f.x,  f.y,  a1h0, a1l0);
            split2(f8.x, f8.y, a1h1, a1l1);
        }
        __syncwarp();   // reads done before next iteration's stores

        float bestdiff = 3.4e38f, bestP = 0.0f;

        for (int e = 0; e < NENS; e++) {
            // ---- layer 1: X[16x8] @ W1[8x64] via m16n8k8 ----
            uint32_t A2h[4][4], A2l[4][4];
            const uint4* w1p = sW1p + (e * 8) * 32 + lane;
            #pragma unroll
            for (int nt = 0; nt < 8; nt++) {
                uint4 w = w1p[nt * 32];              // {hi_b, lo_b, bias0, bias1}
                float cH0 = __uint_as_float(w.z), cH1 = __uint_as_float(w.w);
                float cH2 = cH0, cH3 = cH1;
                float cM0=0,cM1=0,cM2=0,cM3=0;
                mma16808(cH0,cH1,cH2,cH3, a1h0,a1h1, w.x);
                mma16808(cM0,cM1,cM2,cM3, a1h0,a1h1, w.y);
                mma16808(cM0,cM1,cM2,cM3, a1l0,a1l1, w.x);  // chained
                float th0 = fast_tanh_pre(cH0 + cM0);
                float th1 = fast_tanh_pre(cH1 + cM1);
                float th2 = fast_tanh_pre(cH2 + cM2);
                float th3 = fast_tanh_pre(cH3 + cM3);
                int kt = nt >> 1, hh = (nt & 1) * 2;   // C->A remap
                split2(th0, th1, A2h[kt][hh],     A2l[kt][hh]);
                split2(th2, th3, A2h[kt][hh + 1], A2l[kt][hh + 1]);
            }

            // ---- layers 2+3: packed B-frags; w3 folded through tanh ----
            float zp0 = 0.0f, zp1 = 0.0f;
            const uint4* w2p = sW2p + (e * 8) * 4 * 32 + lane;
            for (int nt = 0; nt < 8; nt++) {           // runtime loop (I-cache)
                float4 bw = sBW[(e*8 + nt)*4 + t];     // {b2x, b2y, w3m0, w3m1}
                float cH0=bw.x, cH1=bw.y, cH2=bw.x, cH3=bw.y;
                float cM0=0,cM1=0,cM2=0,cM3=0;
                float cL0=0,cL1=0,cL2=0,cL3=0;
                const uint4* wrow = w2p + nt * (4*32);
                #pragma unroll
                for (int kt = 0; kt < 4; kt++) {
                    uint4 w = wrow[kt * 32];           // {hi_b0,hi_b1,lo_b0,lo_b1}
                    mma16816(cH0,cH1,cH2,cH3, A2h[kt][0],A2h[kt][1],A2h[kt][2],A2h[kt][3], w.x,w.y);
                    mma16816(cM0,cM1,cM2,cM3, A2h[kt][0],A2h[kt][1],A2h[kt][2],A2h[kt][3], w.z,w.w);
                    mma16816(cL0,cL1,cL2,cL3, A2l[kt][0],A2l[kt][1],A2l[kt][2],A2l[kt][3], w.x,w.y);
                }
                // z += th*w3 == const + r*(-2*w3); const folded into b3'
                float r0 = fast_r_pre(cH0 + cM0 + cL0);
                float r1 = fast_r_pre(cH1 + cM1 + cL1);
                float r2 = fast_r_pre(cH2 + cM2 + cL2);
                float r3 = fast_r_pre(cH3 + cM3 + cL3);
                zp0 = fmaf(r0, bw.z, zp0); zp0 = fmaf(r1, bw.w, zp0);
                zp1 = fmaf(r2, bw.z, zp1); zp1 = fmaf(r3, bw.w, zp1);
            }
            // reduce over the 4 lanes of each row-group
            zp0 += __shfl_xor_sync(0xffffffffu, zp0, 1);
            zp0 += __shfl_xor_sync(0xffffffffu, zp0, 2);
            zp1 += __shfl_xor_sync(0xffffffffu, zp1, 1);
            zp1 += __shfl_xor_sync(0xffffffffu, zp1, 2);
            int src = (c & 7) * 4;
            float za = __shfl_sync(0xffffffffu, zp0, src);
            float zb = __shfl_sync(0xffffffffu, zp1, src);
            float z  = ((c < 8) ? za : zb) + sB3[e];   // z is log2e-scaled

            // per-ensemble shock: one parallel get_vel_shock per lane (own side)
            float pc = aPress * fmaf(2.0f, fast_exp_pre(z), 1.0f);
            float rC, hC, vs, Vs;
            get_vel_shock(pc, rho, p, v, sgn, rC, hC, vs, Vs);
            float vsO = __shfl_xor_sync(0xffffffffu, vs, 16);
            float d = fabsf(vs - vsO);        // symmetric: both lanes agree
            if (d < bestdiff) { bestdiff = d; bestP = pc; }
        }

        // final shock recompute, parallel over sides; exchange via shfl
        float rhoC, hC, vstar, vsh;
        get_vel_shock(bestP, rho, p, v, sgn, rhoC, hC, vstar, vsh);
        float vstarO = __shfl_xor_sync(0xffffffffu, vstar, 16);
        float vshO   = __shfl_xor_sync(0xffffffffu, vsh,   16);
        float rhoCO  = __shfl_xor_sync(0xffffffffu, rhoC,  16);
        float hCO    = __shfl_xor_sync(0xffffffffu, hC,    16);

        if (side == 0 && act) {
            // own = Left, other = Right
            float lam = 0.5f * (vstarO + vstar);
            float WC  = fast_rsqrt(1.0f - lam * lam);
            float densCL = WC * rhoC, densCR = WC * rhoCO;

            float f0 = 0.0f, f1 = 0.0f, f2 = 0.0f;
            if (vsh >= 0.0f) { f0 = F[cell*6+0]; f1 = F[cell*6+2]; f2 = F[cell*6+4]; }
            if (vsh < 0.0f && lam > 0.0f) {
                f0 = densCL * lam;
                f1 = densCL * (WC * hC - 1.0f) * lam;
                f2 = (WC * WC * rhoC * hC * lam) * lam + bestP;
            }
            if (lam <= 0.0f && vshO > 0.0f) {
                f0 = densCR * lam;
                f1 = densCR * (WC * hCO - 1.0f) * lam;
                f2 = (WC * WC * rhoCO * hCO * lam) * lam + bestP;
            }
            if (vshO <= 0.0f) { f0 = F[cell*6+1]; f1 = F[cell*6+3]; f2 = F[cell*6+5]; }
            out[cell*3+0] = f0; out[cell*3+1] = f1; out[cell*3+2] = f2;
        }
    }
}

extern "C" void kernel_launch(void* const* d_in, const int* in_sizes, int n_in,
                              void* d_out, int out_size)
{
    const float* P  = (const float*)d_in[0];
    const float* F  = (const float*)d_in[2];
    const float* W1 = (const float*)d_in[5];
    const float* b1 = (const float*)d_in[6];
    const float* W2 = (const float*)d_in[7];
    const float* b2 = (const float*)d_in[8];
    const float* W3 = (const float*)d_in[9];
    const float* b3 = (const float*)d_in[10];
    float* out = (float*)d_out;
    const int N = in_sizes[0] / 6;

    const int nprep = NENS*8*4*32 + NENS*8*32 + NENS*8*4 + NENS;
    prep_kernel<<<(nprep + 255) / 256, 256>>>(W1, W2, b1, b2, W3, b3);

    cudaFuncSetAttribute(solver_mma,
                         cudaFuncAttributeMaxDynamicSharedMemorySize, SMEM_BYTES);
    solver_mma<<<148, NTHREADS, SMEM_BYTES>>>(P, F, out, N);
}

// round 11
// speedup vs baseline: 2.3960x; 1.0212x over previous
#include <cuda_runtime.h>
#include <cuda_bf16.h>
#include <math.h>
#include <stdint.h>

#define NTHREADS 640
#define NWARPS   (NTHREADS/32)
#define NENS 8
#define HID 64

#define TANH_C  2.8853900817779268f   // 2*log2(e) folded into W1,b1,W2,b2
#define LOG2E   1.4426950408889634f   // folded into W3,b3
#define LN2     0.6931471805599453f

// packed weight records in __device__ scratch (allocation-free)
__device__ __align__(16) uint4  g_w2p[NENS * 8 * 4 * 32];   // 131072 B
__device__ __align__(16) uint4  g_w1p[NENS * 8 * 32];       // 32768 B
__device__ __align__(16) float4 g_bw [NENS * 8 * 4];        // 4096 B
__device__ float g_b3s[NENS];

// ---- shared memory byte offsets ----
#define SM_W2P 0
#define SM_W1P (SM_W2P + 131072)
#define SM_BW  (SM_W1P + 32768)            // 163840
#define SM_B3  (SM_BW + 4096)              // 167936
#define SM_X   (SM_B3 + 32)                // 167968
#define SMEM_BYTES (SM_X + NWARPS*16*8*4)  // 178208

// ---- MUFU approx primitives (rel err ~2^-22) ----
__device__ __forceinline__ float fast_rcp(float x) {
    float r; asm("rcp.approx.f32 %0, %1;" : "=f"(r) : "f"(x)); return r;
}
__device__ __forceinline__ float fast_rsqrt(float x) {
    float r; asm("rsqrt.approx.f32 %0, %1;" : "=f"(r) : "f"(x)); return r;
}
__device__ __forceinline__ float fast_sqrt(float x) {
    float r; asm("sqrt.approx.f32 %0, %1;" : "=f"(r) : "f"(x)); return r;
}
__device__ __forceinline__ float fast_log(float x) {
    float l; asm("lg2.approx.f32 %0, %1;" : "=f"(l) : "f"(x)); return l * LN2;
}
__device__ __forceinline__ float fast_ex2(float s) {
    float e; asm("ex2.approx.f32 %0, %1;" : "=f"(e) : "f"(s)); return e;
}

// Quad-batched r_i = 1/(ex2(s_i)+1), one rcp for four values.
// Safe: |s| < ~30 in this net, so products stay < 2^120 (no inf/denorm issues).
__device__ __forceinline__ void quad_r(float s0, float s1, float s2, float s3,
                                       float& r0, float& r1, float& r2, float& r3)
{
    float e0p = fast_ex2(s0) + 1.0f;
    float e1p = fast_ex2(s1) + 1.0f;
    float e2p = fast_ex2(s2) + 1.0f;
    float e3p = fast_ex2(s3) + 1.0f;
    float pa = e0p * e1p, pb = e2p * e3p;
    float q  = fast_rcp(pa * pb);
    float qa = q * pb, qb = q * pa;
    r0 = qa * e1p;  r1 = qa * e0p;
    r2 = qb * e3p;  r3 = qb * e2p;
}

// ---- bf16x2 pack + hi/lo split: v = hi + lo, err ~2^-18 ----
__device__ __forceinline__ void split2(float v0, float v1, uint32_t& hi, uint32_t& lo) {
    __nv_bfloat162 h = __floats2bfloat162_rn(v0, v1);
    hi = *reinterpret_cast<uint32_t*>(&h);
    float f0 = __uint_as_float(hi << 16);
    float f1 = __uint_as_float(hi & 0xffff0000u);
    __nv_bfloat162 l = __floats2bfloat162_rn(v0 - f0, v1 - f1);
    lo = *reinterpret_cast<uint32_t*>(&l);
}

// ---- mma.sync m16n8k16 / m16n8k8, bf16, fp32 accum ----
__device__ __forceinline__ void mma16816(float& c0, float& c1, float& c2, float& c3,
    uint32_t a0, uint32_t a1, uint32_t a2, uint32_t a3, uint32_t b0, uint32_t b1)
{
    asm volatile("mma.sync.aligned.m16n8k16.row.col.f32.bf16.bf16.f32 "
        "{%0,%1,%2,%3},{%4,%5,%6,%7},{%8,%9},{%0,%1,%2,%3};"
        : "+f"(c0), "+f"(c1), "+f"(c2), "+f"(c3)
        : "r"(a0), "r"(a1), "r"(a2), "r"(a3), "r"(b0), "r"(b1));
}
__device__ __forceinline__ void mma16808(float& c0, float& c1, float& c2, float& c3,
    uint32_t a0, uint32_t a1, uint32_t b0)
{
    asm volatile("mma.sync.aligned.m16n8k8.row.col.f32.bf16.bf16.f32 "
        "{%0,%1,%2,%3},{%4,%5},{%6},{%0,%1,%2,%3};"
        : "+f"(c0), "+f"(c1), "+f"(c2), "+f"(c3)
        : "r"(a0), "r"(a1), "r"(b0));
}

// Light vstar-only shock for the ensemble loop (invariants hoisted). 9 MUFU.
__device__ __forceinline__ float vstar_light(float pC, float p, float v, float sgn,
    float rrho, float omv2, float h, float hW, float a2, float irW)
{
    float dp   = p - pC;
    float rpC  = fast_rcp(pC);
    float t04  = 0.4f * dp * rpC;
    float A    = 1.0f + t04;
    float C    = h * dp * rrho - h * h;
    float disc = fmaxf(fmaf(t04, t04, -4.0f * A * C), 0.0f);
    float hC   = (fast_sqrt(disc) + t04) * (0.5f * fast_rcp(A));
    float hCm1 = hC - 1.0f;
    float denj = h * rrho - 0.4f * hC * hCm1 * rpC;
    float j2   = fmaxf((pC - p) * fast_rcp(denj), 1e-12f);
    float rj   = fast_rsqrt(j2);
    float jabs = j2 * rj;
    float Vs   = (a2 * v + sgn * jabs * fast_sqrt(fmaf(a2, omv2, j2))) * fast_rcp(a2 + j2);
    float Ws   = fast_rsqrt(fmaxf(1.0f - Vs * Vs, 1e-12f));
    float rjs  = sgn * rj;
    float num  = hW * v + Ws * (pC - p) * rjs;
    float den  = hW + (pC - p) * (Ws * v * rjs + irW);
    return num * fast_rcp(den);
}

// Full shock (final recompute only).
__device__ __forceinline__ void get_vel_shock(
    float pC, float rho, float p, float v, float sign,
    float& rhoC, float& hC, float& vstar, float& Vs)
{
    float rrho = fast_rcp(rho);
    float h    = fmaf(2.5f * p, rrho, 1.0f);
    float omv2 = 1.0f - v * v;
    float W    = fast_rsqrt(omv2);
    float dp   = p - pC;
    float rpC  = fast_rcp(pC);
    float t04  = 0.4f * dp * rpC;
    float A    = 1.0f + t04;
    float B    = -t04;
    float C    = h * dp * rrho - h * h;
    float disc = fmaxf(fmaf(B, B, -4.0f * A * C), 0.0f);
    hC   = (fast_sqrt(disc) - B) * (0.5f * fast_rcp(A));
    float hCm1 = hC - 1.0f;
    rhoC = 2.5f * pC * fast_rcp(hCm1);
    float denj = h * rrho - 0.4f * hC * hCm1 * rpC;
    float j2   = fmaxf((pC - p) * fast_rcp(denj), 1e-12f);
    float jabs = fast_sqrt(j2);
    float rw   = rho * W;
    float a2   = rw * rw;
    Vs = (a2 * v + sign * jabs * fast_sqrt(fmaf(a2, omv2, j2))) * fast_rcp(a2 + j2);
    float Ws = fast_rsqrt(fmaxf(1.0f - Vs * Vs, 1e-12f));
    float js = sign * jabs;
    float rjs = fast_rcp(js);
    float hW  = h * W;
    float num = hW * v + Ws * (pC - p) * rjs;
    float den = hW + (pC - p) * (Ws * v * rjs + rrho * omv2 * W);
    vstar = num * fast_rcp(den);
}

// ---- prep: build packed fragment tables (all scales folded in) ----
__global__ void prep_kernel(const float* __restrict__ W1, const float* __restrict__ W2,
                            const float* __restrict__ b1, const float* __restrict__ b2,
                            const float* __restrict__ W3, const float* __restrict__ b3)
{
    const int nW2 = NENS*8*4*32, nW1 = NENS*8*32, nBW = NENS*8*4;
    int idx = blockIdx.x * blockDim.x + threadIdx.x;
    if (idx < nW2) {
        int lane = idx & 31, kt = (idx >> 5) & 3, nt = (idx >> 7) & 7, e = idx >> 10;
        int gg = lane >> 2, t = lane & 3;
        int n = nt * 8 + gg;
        int kb = kt * 16 + 2 * t;
        float w00 = TANH_C * W2[(e*HID + kb    )*HID + n];
        float w01 = TANH_C * W2[(e*HID + kb + 1)*HID + n];
        float w10 = TANH_C * W2[(e*HID + kb + 8)*HID + n];
        float w11 = TANH_C * W2[(e*HID + kb + 9)*HID + n];
        uint32_t h0, l0, h1, l1;
        split2(w00, w01, h0, l0);
        split2(w10, w11, h1, l1);
        g_w2p[idx] = make_uint4(h0, h1, l0, l1);
    } else if (idx < nW2 + nW1) {
        int j = idx - nW2;
        int lane = j & 31, nt = (j >> 5) & 7, e = j >> 8;
        int gg = lane >> 2, t = lane & 3;
        int n = nt * 8 + gg;
        int k = 2 * t;
        float w0 = (k     < 6) ? TANH_C * W1[(e*6 + k    )*HID + n] : 0.0f;
        float w1 = (k + 1 < 6) ? TANH_C * W1[(e*6 + k + 1)*HID + n] : 0.0f;
        uint32_t h0, l0;
        split2(w0, w1, h0, l0);
        float bias0 = TANH_C * b1[e*HID + nt*8 + 2*t];
        float bias1 = TANH_C * b1[e*HID + nt*8 + 2*t + 1];
        g_w1p[j] = make_uint4(h0, l0, __float_as_uint(bias0), __float_as_uint(bias1));
    } else if (idx < nW2 + nW1 + nBW) {
        int j = idx - nW2 - nW1;
        int t = j & 3, nt = (j >> 2) & 7, e = j >> 5;
        int base = e*HID + nt*8 + 2*t;
        g_bw[j] = make_float4(TANH_C * b2[base], TANH_C * b2[base+1],
                              -2.0f * LOG2E * W3[base], -2.0f * LOG2E * W3[base+1]);
    } else if (idx < nW2 + nW1 + nBW + NENS) {
        int e = idx - nW2 - nW1 - nBW;
        float s = b3[e];
        for (int j = 0; j < HID; j++) s += W3[e*HID + j];
        g_b3s[e] = LOG2E * s;
    }
}

__global__ void __launch_bounds__(NTHREADS, 1)
solver_mma(const float* __restrict__ P, const float* __restrict__ F,
           float* __restrict__ out, int N)
{
    extern __shared__ char smem[];
    uint4*  sW2p = (uint4*)(smem + SM_W2P);
    uint4*  sW1p = (uint4*)(smem + SM_W1P);
    float4* sBW  = (float4*)(smem + SM_BW);
    float*  sB3  = (float*)(smem + SM_B3);
    float*  sX   = (float*)(smem + SM_X);

    // cooperative smem fill
    {
        const int4* s1 = (const int4*)g_w2p;  int4* d1 = (int4*)sW2p;
        for (int i = threadIdx.x; i < NENS*8*4*32; i += NTHREADS) d1[i] = s1[i];
        const int4* s2 = (const int4*)g_w1p;  int4* d2 = (int4*)sW1p;
        for (int i = threadIdx.x; i < NENS*8*32; i += NTHREADS) d2[i] = s2[i];
        const int4* s3 = (const int4*)g_bw;   int4* d3 = (int4*)sBW;
        for (int i = threadIdx.x; i < NENS*8*4; i += NTHREADS) d3[i] = s3[i];
        if (threadIdx.x < NENS) sB3[threadIdx.x] = g_b3s[threadIdx.x];
    }
    __syncthreads();

    const int lane = threadIdx.x & 31, wid = threadIdx.x >> 5;
    const int g = lane >> 2, t = lane & 3;
    const int side = lane >> 4;          // 0 = Left state, 1 = Right state
    const int c    = lane & 15;          // cell index within tile
    const float sgn = side ? 1.0f : -1.0f;
    const int ntiles = (N + 15) >> 4;
    float* Xw = sX + wid * 128;

    for (int tile = blockIdx.x * NWARPS + wid; tile < ntiles; tile += gridDim.x * NWARPS) {
        const int cell = tile * 16 + c;
        const bool act = (cell < N);

        // each lane owns ONE side of one cell
        float rho = 1.0f, p = 1.0f, v = 0.0f;
        if (act) {
            rho = P[cell*6 + side];
            p   = P[cell*6 + 2 + side];
            v   = P[cell*6 + 4 + side];
            Xw[c*8 + side]     = fast_log(rho);
            Xw[c*8 + 2 + side] = fast_log(p);
            Xw[c*8 + 4 + side] = v;
        } else {
            Xw[c*8 + side]     = 0.0f;
            Xw[c*8 + 2 + side] = 0.0f;
            Xw[c*8 + 4 + side] = 0.0f;
        }
        if (side == 0) { Xw[c*8 + 6] = 0.0f; Xw[c*8 + 7] = 0.0f; }
        __syncwarp();
        const float aPress = fmaxf(p, __shfl_xor_sync(0xffffffffu, p, 16));

        // per-lane shock invariants (hoisted out of the ensemble loop)
        const float rrho = fast_rcp(rho);
        const float omv2 = 1.0f - v * v;
        const float Wl   = fast_rsqrt(omv2);
        const float hh   = fmaf(2.5f * p, rrho, 1.0f);
        const float hW   = hh * Wl;
        const float rw   = rho * Wl;
        const float a2   = rw * rw;
        const float irW  = rrho * omv2 * Wl;

        // layer1 A-fragments (rows = cells g, g+8; k = 2t,2t+1)
        uint32_t a1h0, a1l0, a1h1, a1l1;
        {
            float2 f  = *(float2*)&Xw[g*8 + 2*t];
            float2 f8 = *(float2*)&Xw[(g+8)*8 + 2*t];
            split2(f.x,  f.y,  a1h0, a1l0);
            split2(f8.x, f8.y, a1h1, a1l1);
        }
        __syncwarp();   // reads done before next iteration's stores

        float bestdiff = 3.4e38f, bestP = 0.0f;

        for (int e = 0; e < NENS; e++) {
            // ---- layer 1: X[16x8] @ W1[8x64] via m16n8k8 ----
            uint32_t A2h[4][4], A2l[4][4];
            const uint4* w1p = sW1p + (e * 8) * 32 + lane;
            #pragma unroll
            for (int nt = 0; nt < 8; nt++) {
                uint4 w = w1p[nt * 32];              // {hi_b, lo_b, bias0, bias1}
                float cH0 = __uint_as_float(w.z), cH1 = __uint_as_float(w.w);
                float cH2 = cH0, cH3 = cH1;
                float cM0=0,cM1=0,cM2=0,cM3=0;
                mma16808(cH0,cH1,cH2,cH3, a1h0,a1h1, w.x);
                mma16808(cM0,cM1,cM2,cM3, a1h0,a1h1, w.y);
                mma16808(cM0,cM1,cM2,cM3, a1l0,a1l1, w.x);  // chained
                float r0, r1, r2, r3;
                quad_r(cH0+cM0, cH1+cM1, cH2+cM2, cH3+cM3, r0, r1, r2, r3);
                float th0 = fmaf(-2.0f, r0, 1.0f);
                float th1 = fmaf(-2.0f, r1, 1.0f);
                float th2 = fmaf(-2.0f, r2, 1.0f);
                float th3 = fmaf(-2.0f, r3, 1.0f);
                int kt = nt >> 1, hhp = (nt & 1) * 2;   // C->A remap
                split2(th0, th1, A2h[kt][hhp],     A2l[kt][hhp]);
                split2(th2, th3, A2h[kt][hhp + 1], A2l[kt][hhp + 1]);
            }

            // ---- layers 2+3: packed B-frags; w3 folded through tanh ----
            float zp0 = 0.0f, zp1 = 0.0f;
            const uint4* w2p = sW2p + (e * 8) * 4 * 32 + lane;
            #pragma unroll 2
            for (int nt = 0; nt < 8; nt++) {
                float4 bw = sBW[(e*8 + nt)*4 + t];     // {b2x, b2y, w3m0, w3m1}
                float cH0=bw.x, cH1=bw.y, cH2=bw.x, cH3=bw.y;
                float cM0=0,cM1=0,cM2=0,cM3=0;
                float cL0=0,cL1=0,cL2=0,cL3=0;
                const uint4* wrow = w2p + nt * (4*32);
                #pragma unroll
                for (int kt = 0; kt < 4; kt++) {
                    uint4 w = wrow[kt * 32];           // {hi_b0,hi_b1,lo_b0,lo_b1}
                    mma16816(cH0,cH1,cH2,cH3, A2h[kt][0],A2h[kt][1],A2h[kt][2],A2h[kt][3], w.x,w.y);
                    mma16816(cM0,cM1,cM2,cM3, A2h[kt][0],A2h[kt][1],A2h[kt][2],A2h[kt][3], w.z,w.w);
                    mma16816(cL0,cL1,cL2,cL3, A2l[kt][0],A2l[kt][1],A2l[kt][2],A2l[kt][3], w.x,w.y);
                }
                float r0, r1, r2, r3;
                quad_r(cH0+cM0+cL0, cH1+cM1+cL1, cH2+cM2+cL2, cH3+cM3+cL3,
                       r0, r1, r2, r3);
                zp0 = fmaf(r0, bw.z, zp0); zp0 = fmaf(r1, bw.w, zp0);
                zp1 = fmaf(r2, bw.z, zp1); zp1 = fmaf(r3, bw.w, zp1);
            }
            // reduce over the 4 lanes of each row-group
            zp0 += __shfl_xor_sync(0xffffffffu, zp0, 1);
            zp0 += __shfl_xor_sync(0xffffffffu, zp0, 2);
            zp1 += __shfl_xor_sync(0xffffffffu, zp1, 1);
            zp1 += __shfl_xor_sync(0xffffffffu, zp1, 2);
            int src = (c & 7) * 4;
            float za = __shfl_sync(0xffffffffu, zp0, src);
            float zb = __shfl_sync(0xffffffffu, zp1, src);
            float z  = ((c < 8) ? za : zb) + sB3[e];   // log2e-scaled

            // per-ensemble shock: light, per-side lane, invariants hoisted
            float pc = aPress * fmaf(2.0f, fast_ex2(z), 1.0f);
            float vs = vstar_light(pc, p, v, sgn, rrho, omv2, hh, hW, a2, irW);
            float vsO = __shfl_xor_sync(0xffffffffu, vs, 16);
            float d = fabsf(vs - vsO);        // symmetric: both lanes agree
            if (d < bestdiff) { bestdiff = d; bestP = pc; }
        }

        // final shock recompute, parallel over sides; exchange via shfl
        float rhoC, hC, vstar, vsh;
        get_vel_shock(bestP, rho, p, v, sgn, rhoC, hC, vstar, vsh);
        float vstarO = __shfl_xor_sync(0xffffffffu, vstar, 16);
        float vshO   = __shfl_xor_sync(0xffffffffu, vsh,   16);
        float rhoCO  = __shfl_xor_sync(0xffffffffu, rhoC,  16);
        float hCO    = __shfl_xor_sync(0xffffffffu, hC,    16);

        if (side == 0 && act) {
            // own = Left, other = Right
            float lam = 0.5f * (vstarO + vstar);
            float WC  = fast_rsqrt(1.0f - lam * lam);
            float densCL = WC * rhoC, densCR = WC * rhoCO;

            float f0 = 0.0f, f1 = 0.0f, f2 = 0.0f;
            if (vsh >= 0.0f) { f0 = F[cell*6+0]; f1 = F[cell*6+2]; f2 = F[cell*6+4]; }
            if (vsh < 0.0f && lam > 0.0f) {
                f0 = densCL * lam;
                f1 = densCL * (WC * hC - 1.0f) * lam;
                f2 = (WC * WC * rhoC * hC * lam) * lam + bestP;
            }
            if (lam <= 0.0f && vshO > 0.0f) {
                f0 = densCR * lam;
                f1 = densCR * (WC * hCO - 1.0f) * lam;
                f2 = (WC * WC * rhoCO * hCO * lam) * lam + bestP;
            }
            if (vshO <= 0.0f) { f0 = F[cell*6+1]; f1 = F[cell*6+3]; f2 = F[cell*6+5]; }
            out[cell*3+0] = f0; out[cell*3+1] = f1; out[cell*3+2] = f2;
        }
    }
}

extern "C" void kernel_launch(void* const* d_in, const int* in_sizes, int n_in,
                              void* d_out, int out_size)
{
    const float* P  = (const float*)d_in[0];
    const float* F  = (const float*)d_in[2];
    const float* W1 = (const float*)d_in[5];
    const float* b1 = (const float*)d_in[6];
    const float* W2 = (const float*)d_in[7];
    const float* b2 = (const float*)d_in[8];
    const float* W3 = (const float*)d_in[9];
    const float* b3 = (const float*)d_in[10];
    float* out = (float*)d_out;
    const int N = in_sizes[0] / 6;

    const int nprep = NENS*8*4*32 + NENS*8*32 + NENS*8*4 + NENS;
    prep_kernel<<<(nprep + 255) / 256, 256>>>(W1, W2, b1, b2, W3, b3);

    cudaFuncSetAttribute(solver_mma,
                         cudaFuncAttributeMaxDynamicSharedMemorySize, SMEM_BYTES);
    solver_mma<<<148, NTHREADS, SMEM_BYTES>>>(P, F, out, N);
}

// round 12
// speedup vs baseline: 2.4077x; 1.0049x over previous
#include <cuda_runtime.h>
#include <cuda_bf16.h>
#include <math.h>
#include <stdint.h>

#define NTHREADS 640
#define NWARPS   (NTHREADS/32)
#define NENS 8
#define HID 64

#define TANH_C  2.8853900817779268f   // 2*log2(e) folded into W1,b1,W2,b2
#define LOG2E   1.4426950408889634f   // folded into W3,b3
#define LN2     0.6931471805599453f

// packed weight records in __device__ scratch (allocation-free)
// W2: [e][nt(8)][kt(4)][lane(32)] uint4 {hi_b0,hi_b1,lo_b0,lo_b1} of (-2*TANH_C*W2)
// W1: [e][nt(8)][lane(32)]        uint4 {hi_b0, lo_b0, bias0, bias1} (TANH_C-scaled)
// BW: [e][nt(8)][t(4)]            float4 {b2'.x, b2'.y, -2*log2e*w3.x, -2*log2e*w3.y}
//                                  where b2' = TANH_C*(b2 + colsum(W2))
__device__ __align__(16) uint4  g_w2p[NENS * 8 * 4 * 32];   // 131072 B
__device__ __align__(16) uint4  g_w1p[NENS * 8 * 32];       // 32768 B
__device__ __align__(16) float4 g_bw [NENS * 8 * 4];        // 4096 B
__device__ float g_b3s[NENS];

// ---- shared memory byte offsets ----
#define SM_W2P 0
#define SM_W1P (SM_W2P + 131072)
#define SM_BW  (SM_W1P + 32768)            // 163840
#define SM_B3  (SM_BW + 4096)              // 167936
#define SM_X   (SM_B3 + 32)                // 167968
#define SMEM_BYTES (SM_X + NWARPS*16*8*4)  // 178208

// ---- MUFU approx primitives (rel err ~2^-22) ----
__device__ __forceinline__ float fast_rcp(float x) {
    float r; asm("rcp.approx.f32 %0, %1;" : "=f"(r) : "f"(x)); return r;
}
__device__ __forceinline__ float fast_rsqrt(float x) {
    float r; asm("rsqrt.approx.f32 %0, %1;" : "=f"(r) : "f"(x)); return r;
}
__device__ __forceinline__ float fast_sqrt(float x) {
    float r; asm("sqrt.approx.f32 %0, %1;" : "=f"(r) : "f"(x)); return r;
}
__device__ __forceinline__ float fast_log(float x) {
    float l; asm("lg2.approx.f32 %0, %1;" : "=f"(l) : "f"(x)); return l * LN2;
}
__device__ __forceinline__ float fast_ex2(float s) {
    float e; asm("ex2.approx.f32 %0, %1;" : "=f"(e) : "f"(s)); return e;
}

// Quad-batched r_i = 1/(ex2(s_i)+1), one rcp for four values.
__device__ __forceinline__ void quad_r(float s0, float s1, float s2, float s3,
                                       float& r0, float& r1, float& r2, float& r3)
{
    float e0p = fast_ex2(s0) + 1.0f;
    float e1p = fast_ex2(s1) + 1.0f;
    float e2p = fast_ex2(s2) + 1.0f;
    float e3p = fast_ex2(s3) + 1.0f;
    float pa = e0p * e1p, pb = e2p * e3p;
    float q  = fast_rcp(pa * pb);
    float qa = q * pb, qb = q * pa;
    r0 = qa * e1p;  r1 = qa * e0p;
    r2 = qb * e3p;  r3 = qb * e2p;
}

// ---- bf16x2 pack + hi/lo split: v = hi + lo, err ~2^-18 ----
__device__ __forceinline__ void split2(float v0, float v1, uint32_t& hi, uint32_t& lo) {
    __nv_bfloat162 h = __floats2bfloat162_rn(v0, v1);
    hi = *reinterpret_cast<uint32_t*>(&h);
    float f0 = __uint_as_float(hi << 16);
    float f1 = __uint_as_float(hi & 0xffff0000u);
    __nv_bfloat162 l = __floats2bfloat162_rn(v0 - f0, v1 - f1);
    lo = *reinterpret_cast<uint32_t*>(&l);
}

// ---- mma.sync m16n8k16 / m16n8k8, bf16, fp32 accum ----
__device__ __forceinline__ void mma16816(float& c0, float& c1, float& c2, float& c3,
    uint32_t a0, uint32_t a1, uint32_t a2, uint32_t a3, uint32_t b0, uint32_t b1)
{
    asm volatile("mma.sync.aligned.m16n8k16.row.col.f32.bf16.bf16.f32 "
        "{%0,%1,%2,%3},{%4,%5,%6,%7},{%8,%9},{%0,%1,%2,%3};"
        : "+f"(c0), "+f"(c1), "+f"(c2), "+f"(c3)
        : "r"(a0), "r"(a1), "r"(a2), "r"(a3), "r"(b0), "r"(b1));
}
__device__ __forceinline__ void mma16808(float& c0, float& c1, float& c2, float& c3,
    uint32_t a0, uint32_t a1, uint32_t b0)
{
    asm volatile("mma.sync.aligned.m16n8k8.row.col.f32.bf16.bf16.f32 "
        "{%0,%1,%2,%3},{%4,%5},{%6},{%0,%1,%2,%3};"
        : "+f"(c0), "+f"(c1), "+f"(c2), "+f"(c3)
        : "r"(a0), "r"(a1), "r"(b0));
}

// Light vstar-only shock for the ensemble loop (invariants hoisted). 9 MUFU.
__device__ __forceinline__ float vstar_light(float pC, float p, float v, float sgn,
    float rrho, float omv2, float h, float hW, float a2, float irW)
{
    float dp   = p - pC;
    float rpC  = fast_rcp(pC);
    float t04  = 0.4f * dp * rpC;
    float A    = 1.0f + t04;
    float C    = h * dp * rrho - h * h;
    float disc = fmaxf(fmaf(t04, t04, -4.0f * A * C), 0.0f);
    float hC   = (fast_sqrt(disc) + t04) * (0.5f * fast_rcp(A));
    float hCm1 = hC - 1.0f;
    float denj = h * rrho - 0.4f * hC * hCm1 * rpC;
    float j2   = fmaxf((pC - p) * fast_rcp(denj), 1e-12f);
    float rj   = fast_rsqrt(j2);
    float jabs = j2 * rj;
    float Vs   = (a2 * v + sgn * jabs * fast_sqrt(fmaf(a2, omv2, j2))) * fast_rcp(a2 + j2);
    float Ws   = fast_rsqrt(fmaxf(1.0f - Vs * Vs, 1e-12f));
    float rjs  = sgn * rj;
    float num  = hW * v + Ws * (pC - p) * rjs;
    float den  = hW + (pC - p) * (Ws * v * rjs + irW);
    return num * fast_rcp(den);
}

// Full shock (final recompute only).
__device__ __forceinline__ void get_vel_shock(
    float pC, float rho, float p, float v, float sign,
    float& rhoC, float& hC, float& vstar, float& Vs)
{
    float rrho = fast_rcp(rho);
    float h    = fmaf(2.5f * p, rrho, 1.0f);
    float omv2 = 1.0f - v * v;
    float W    = fast_rsqrt(omv2);
    float dp   = p - pC;
    float rpC  = fast_rcp(pC);
    float t04  = 0.4f * dp * rpC;
    float A    = 1.0f + t04;
    float B    = -t04;
    float C    = h * dp * rrho - h * h;
    float disc = fmaxf(fmaf(B, B, -4.0f * A * C), 0.0f);
    hC   = (fast_sqrt(disc) - B) * (0.5f * fast_rcp(A));
    float hCm1 = hC - 1.0f;
    rhoC = 2.5f * pC * fast_rcp(hCm1);
    float denj = h * rrho - 0.4f * hC * hCm1 * rpC;
    float j2   = fmaxf((pC - p) * fast_rcp(denj), 1e-12f);
    float jabs = fast_sqrt(j2);
    float rw   = rho * W;
    float a2   = rw * rw;
    Vs = (a2 * v + sign * jabs * fast_sqrt(fmaf(a2, omv2, j2))) * fast_rcp(a2 + j2);
    float Ws = fast_rsqrt(fmaxf(1.0f - Vs * Vs, 1e-12f));
    float js = sign * jabs;
    float rjs = fast_rcp(js);
    float hW  = h * W;
    float num = hW * v + Ws * (pC - p) * rjs;
    float den = hW + (pC - p) * (Ws * v * rjs + rrho * omv2 * W);
    vstar = num * fast_rcp(den);
}

// ---- prep: build packed fragment tables (all scales + affine folds) ----
__global__ void prep_kernel(const float* __restrict__ W1, const float* __restrict__ W2,
                            const float* __restrict__ b1, const float* __restrict__ b2,
                            const float* __restrict__ W3, const float* __restrict__ b3)
{
    const int nW2 = NENS*8*4*32, nW1 = NENS*8*32, nBW = NENS*8*4;
    int idx = blockIdx.x * blockDim.x + threadIdx.x;
    if (idx < nW2) {                               // B-frags of (-2*TANH_C*W2)
        int lane = idx & 31, kt = (idx >> 5) & 3, nt = (idx >> 7) & 7, e = idx >> 10;
        int gg = lane >> 2, t = lane & 3;
        int n = nt * 8 + gg;
        int kb = kt * 16 + 2 * t;
        const float s = -2.0f * TANH_C;
        float w00 = s * W2[(e*HID + kb    )*HID + n], w01 = s * W2[(e*HID + kb + 1)*HID + n];
        float w10 = s * W2[(e*HID + kb + 8)*HID + n], w11 = s * W2[(e*HID + kb + 9)*HID + n];
        uint32_t h0, l0, h1, l1;
        split2(w00, w01, h0, l0);
        split2(w10, w11, h1, l1);
        g_w2p[idx] = make_uint4(h0, h1, l0, l1);
    } else if (idx < nW2 + nW1) {                  // W1 packed + bias (TANH_C-scaled)
        int j = idx - nW2;
        int lane = j & 31, nt = (j >> 5) & 7, e = j >> 8;
        int gg = lane >> 2, t = lane & 3;
        int n = nt * 8 + gg;
        int k = 2 * t;
        float w0 = (k     < 6) ? TANH_C * W1[(e*6 + k    )*HID + n] : 0.0f;
        float w1 = (k + 1 < 6) ? TANH_C * W1[(e*6 + k + 1)*HID + n] : 0.0f;
        uint32_t h0, l0;
        split2(w0, w1, h0, l0);
        float bias0 = TANH_C * b1[e*HID + nt*8 + 2*t];
        float bias1 = TANH_C * b1[e*HID + nt*8 + 2*t + 1];
        g_w1p[j] = make_uint4(h0, l0, __float_as_uint(bias0), __float_as_uint(bias1));
    } else if (idx < nW2 + nW1 + nBW) {            // b2' = TANH_C*(b2 + colsum W2); w3' = -2*log2e*w3
        int j = idx - nW2 - nW1;
        int t = j & 3, nt = (j >> 2) & 7, e = j >> 5;
        int base = e*HID + nt*8 + 2*t;
        float cs0 = b2[base], cs1 = b2[base + 1];
        for (int k = 0; k < HID; k++) {
            cs0 += W2[(e*HID + k)*HID + (nt*8 + 2*t)];
            cs1 += W2[(e*HID + k)*HID + (nt*8 + 2*t + 1)];
        }
        g_bw[j] = make_float4(TANH_C * cs0, TANH_C * cs1,
                              -2.0f * LOG2E * W3[base], -2.0f * LOG2E * W3[base+1]);
    } else if (idx < nW2 + nW1 + nBW + NENS) {     // b3' = log2e*(b3 + sum w3)
        int e = idx - nW2 - nW1 - nBW;
        float s = b3[e];
        for (int j = 0; j < HID; j++) s += W3[e*HID + j];
        g_b3s[e] = LOG2E * s;
    }
}

__global__ void __launch_bounds__(NTHREADS, 1)
solver_mma(const float* __restrict__ P, const float* __restrict__ F,
           float* __restrict__ out, int N)
{
    extern __shared__ char smem[];
    uint4*  sW2p = (uint4*)(smem + SM_W2P);
    uint4*  sW1p = (uint4*)(smem + SM_W1P);
    float4* sBW  = (float4*)(smem + SM_BW);
    float*  sB3  = (float*)(smem + SM_B3);
    float*  sX   = (float*)(smem + SM_X);

    // cooperative smem fill
    {
        const int4* s1 = (const int4*)g_w2p;  int4* d1 = (int4*)sW2p;
        for (int i = threadIdx.x; i < NENS*8*4*32; i += NTHREADS) d1[i] = s1[i];
        const int4* s2 = (const int4*)g_w1p;  int4* d2 = (int4*)sW1p;
        for (int i = threadIdx.x; i < NENS*8*32; i += NTHREADS) d2[i] = s2[i];
        const int4* s3 = (const int4*)g_bw;   int4* d3 = (int4*)sBW;
        for (int i = threadIdx.x; i < NENS*8*4; i += NTHREADS) d3[i] = s3[i];
        if (threadIdx.x < NENS) sB3[threadIdx.x] = g_b3s[threadIdx.x];
    }
    __syncthreads();

    const int lane = threadIdx.x & 31, wid = threadIdx.x >> 5;
    const int g = lane >> 2, t = lane & 3;
    const int side = lane >> 4;          // 0 = Left state, 1 = Right state
    const int c    = lane & 15;          // cell index within tile
    const float sgn = side ? 1.0f : -1.0f;
    const int ntiles = (N + 15) >> 4;
    float* Xw = sX + wid * 128;

    for (int tile = blockIdx.x * NWARPS + wid; tile < ntiles; tile += gridDim.x * NWARPS) {
        const int cell = tile * 16 + c;
        const bool act = (cell < N);

        // each lane owns ONE side of one cell; prefetch flux early (latency
        // hidden under the ensemble loop)
        float rho = 1.0f, p = 1.0f, v = 0.0f;
        float fx0 = 0.0f, fx1 = 0.0f, fx2 = 0.0f;
        if (act) {
            rho = P[cell*6 + side];
            p   = P[cell*6 + 2 + side];
            v   = P[cell*6 + 4 + side];
            fx0 = F[cell*6 + side];
            fx1 = F[cell*6 + 2 + side];
            fx2 = F[cell*6 + 4 + side];
            Xw[c*8 + side]     = fast_log(rho);
            Xw[c*8 + 2 + side] = fast_log(p);
            Xw[c*8 + 4 + side] = v;
        } else {
            Xw[c*8 + side]     = 0.0f;
            Xw[c*8 + 2 + side] = 0.0f;
            Xw[c*8 + 4 + side] = 0.0f;
        }
        if (side == 0) { Xw[c*8 + 6] = 0.0f; Xw[c*8 + 7] = 0.0f; }
        __syncwarp();
        const float aPress = fmaxf(p, __shfl_xor_sync(0xffffffffu, p, 16));

        // per-lane shock invariants (hoisted out of the ensemble loop)
        const float rrho = fast_rcp(rho);
        const float omv2 = 1.0f - v * v;
        const float Wl   = fast_rsqrt(omv2);
        const float hh   = fmaf(2.5f * p, rrho, 1.0f);
        const float hW   = hh * Wl;
        const float rw   = rho * Wl;
        const float a2   = rw * rw;
        const float irW  = rrho * omv2 * Wl;

        // layer1 A-fragments (rows = cells g, g+8; k = 2t,2t+1)
        uint32_t a1h0, a1l0, a1h1, a1l1;
        {
            float2 f  = *(float2*)&Xw[g*8 + 2*t];
            float2 f8 = *(float2*)&Xw[(g+8)*8 + 2*t];
            split2(f.x,  f.y,  a1h0, a1l0);
            split2(f8.x, f8.y, a1h1, a1l1);
        }
        __syncwarp();   // reads done before next iteration's stores

        float bestdiff = 3.4e38f, bestP = 0.0f;

        for (int e = 0; e < NENS; e++) {
            // ---- layer 1: X[16x8] @ W1[8x64] via m16n8k8; feed r straight on ----
            uint32_t A2h[4][4], A2l[4][4];
            const uint4* w1p = sW1p + (e * 8) * 32 + lane;
            #pragma unroll
            for (int nt = 0; nt < 8; nt++) {
                uint4 w = w1p[nt * 32];              // {hi_b, lo_b, bias0, bias1}
                float cH0 = __uint_as_float(w.z), cH1 = __uint_as_float(w.w);
                float cH2 = cH0, cH3 = cH1;
                float cM0=0,cM1=0,cM2=0,cM3=0;
                mma16808(cH0,cH1,cH2,cH3, a1h0,a1h1, w.x);
                mma16808(cM0,cM1,cM2,cM3, a1h0,a1h1, w.y);
                mma16808(cM0,cM1,cM2,cM3, a1l0,a1l1, w.x);  // chained
                float r0, r1, r2, r3;
                quad_r(cH0+cM0, cH1+cM1, cH2+cM2, cH3+cM3, r0, r1, r2, r3);
                // (1-2r) affine is folded into W2'/b2' -> split r directly
                int kt = nt >> 1, hhp = (nt & 1) * 2;   // C->A remap
                split2(r0, r1, A2h[kt][hhp],     A2l[kt][hhp]);
                split2(r2, r3, A2h[kt][hhp + 1], A2l[kt][hhp + 1]);
            }

            // ---- layers 2+3: packed B-frags; both affine maps pre-folded ----
            float zp0 = 0.0f, zp1 = 0.0f;
            const uint4* w2p = sW2p + (e * 8) * 4 * 32 + lane;
            #pragma unroll 2
            for (int nt = 0; nt < 8; nt++) {
                float4 bw = sBW[(e*8 + nt)*4 + t];     // {b2'x, b2'y, w3m0, w3m1}
                float cH0=bw.x, cH1=bw.y, cH2=bw.x, cH3=bw.y;
                float cM0=0,cM1=0,cM2=0,cM3=0;
                float cL0=0,cL1=0,cL2=0,cL3=0;
                const uint4* wrow = w2p + nt * (4*32);
                #pragma unroll
                for (int kt = 0; kt < 4; kt++) {
                    uint4 w = wrow[kt * 32];           // {hi_b0,hi_b1,lo_b0,lo_b1}
                    mma16816(cH0,cH1,cH2,cH3, A2h[kt][0],A2h[kt][1],A2h[kt][2],A2h[kt][3], w.x,w.y);
                    mma16816(cM0,cM1,cM2,cM3, A2h[kt][0],A2h[kt][1],A2h[kt][2],A2h[kt][3], w.z,w.w);
                    mma16816(cL0,cL1,cL2,cL3, A2l[kt][0],A2l[kt][1],A2l[kt][2],A2l[kt][3], w.x,w.y);
                }
                float r0, r1, r2, r3;
                quad_r(cH0+cM0+cL0, cH1+cM1+cL1, cH2+cM2+cL2, cH3+cM3+cL3,
                       r0, r1, r2, r3);
                zp0 = fmaf(r0, bw.z, zp0); zp0 = fmaf(r1, bw.w, zp0);
                zp1 = fmaf(r2, bw.z, zp1); zp1 = fmaf(r3, bw.w, zp1);
            }
            // reduce over the 4 lanes of each row-group
            zp0 += __shfl_xor_sync(0xffffffffu, zp0, 1);
            zp0 += __shfl_xor_sync(0xffffffffu, zp0, 2);
            zp1 += __shfl_xor_sync(0xffffffffu, zp1, 1);
            zp1 += __shfl_xor_sync(0xffffffffu, zp1, 2);
            int src = (c & 7) * 4;
            float za = __shfl_sync(0xffffffffu, zp0, src);
            float zb = __shfl_sync(0xffffffffu, zp1, src);
            float z  = ((c < 8) ? za : zb) + sB3[e];   // log2e-scaled

            // per-ensemble shock: light, per-side lane, invariants hoisted
            float pc = aPress * fmaf(2.0f, fast_ex2(z), 1.0f);
            float vs = vstar_light(pc, p, v, sgn, rrho, omv2, hh, hW, a2, irW);
            float vsO = __shfl_xor_sync(0xffffffffu, vs, 16);
            float d = fabsf(vs - vsO);        // symmetric: both lanes agree
            if (d < bestdiff) { bestdiff = d; bestP = pc; }
        }

        // final shock recompute, parallel over sides; exchange via shfl
        float rhoC, hC, vstar, vsh;
        get_vel_shock(bestP, rho, p, v, sgn, rhoC, hC, vstar, vsh);
        float vstarO = __shfl_xor_sync(0xffffffffu, vstar, 16);
        float vshO   = __shfl_xor_sync(0xffffffffu, vsh,   16);
        float rhoCO  = __shfl_xor_sync(0xffffffffu, rhoC,  16);
        float hCO    = __shfl_xor_sync(0xffffffffu, hC,    16);
        float fR0    = __shfl_xor_sync(0xffffffffu, fx0,   16);
        float fR1    = __shfl_xor_sync(0xffffffffu, fx1,   16);
        float fR2    = __shfl_xor_sync(0xffffffffu, fx2,   16);

        if (side == 0 && act) {
            // own = Left, other = Right
            float lam = 0.5f * (vstarO + vstar);
            float WC  = fast_rsqrt(1.0f - lam * lam);
            float densCL = WC * rhoC, densCR = WC * rhoCO;

            float f0 = 0.0f, f1 = 0.0f, f2 = 0.0f;
            if (vsh >= 0.0f) { f0 = fx0; f1 = fx1; f2 = fx2; }
            if (vsh < 0.0f && lam > 0.0f) {
                f0 = densCL * lam;
                f1 = densCL * (WC * hC - 1.0f) * lam;
                f2 = (WC * WC * rhoC * hC * lam) * lam + bestP;
            }
            if (lam <= 0.0f && vshO > 0.0f) {
                f0 = densCR * lam;
                f1 = densCR * (WC * hCO - 1.0f) * lam;
                f2 = (WC * WC * rhoCO * hCO * lam) * lam + bestP;
            }
            if (vshO <= 0.0f) { f0 = fR0; f1 = fR1; f2 = fR2; }
            out[cell*3+0] = f0; out[cell*3+1] = f1; out[cell*3+2] = f2;
        }
    }
}

extern "C" void kernel_launch(void* const* d_in, const int* in_sizes, int n_in,
                              void* d_out, int out_size)
{
    const float* P  = (const float*)d_in[0];
    const float* F  = (const float*)d_in[2];
    const float* W1 = (const float*)d_in[5];
    const float* b1 = (const float*)d_in[6];
    const float* W2 = (const float*)d_in[7];
    const float* b2 = (const float*)d_in[8];
    const float* W3 = (const float*)d_in[9];
    const float* b3 = (const float*)d_in[10];
    float* out = (float*)d_out;
    const int N = in_sizes[0] / 6;

    const int nprep = NENS*8*4*32 + NENS*8*32 + NENS*8*4 + NENS;
    prep_kernel<<<(nprep + 255) / 256, 256>>>(W1, W2, b1, b2, W3, b3);

    cudaFuncSetAttribute(solver_mma,
                         cudaFuncAttributeMaxDynamicSharedMemorySize, SMEM_BYTES);
    solver_mma<<<148, NTHREADS, SMEM_BYTES>>>(P, F, out, N);
}

// round 13
// speedup vs baseline: 2.4430x; 1.0147x over previous
#include <cuda_runtime.h>
#include <cuda_bf16.h>
#include <math.h>
#include <stdint.h>

#define NTHREADS 640
#define NWARPS   (NTHREADS/32)
#define NENS 8
#define HID 64

#define TANH_C  2.8853900817779268f   // 2*log2(e) folded into W1,b1,W2,b2
#define LOG2E   1.4426950408889634f   // folded into W3,b3
#define LN2     0.6931471805599453f

// packed weight records in __device__ scratch (allocation-free)
__device__ __align__(16) uint4  g_w2p[NENS * 8 * 4 * 32];   // 131072 B
__device__ __align__(16) uint4  g_w1p[NENS * 8 * 32];       // 32768 B
__device__ __align__(16) float4 g_bw [NENS * 8 * 4];        // 4096 B
__device__ float g_b3s[NENS];

// ---- shared memory byte offsets ----
#define SM_W2P 0
#define SM_W1P (SM_W2P + 131072)
#define SM_BW  (SM_W1P + 32768)            // 163840
#define SM_B3  (SM_BW + 4096)              // 167936
#define SM_X   (SM_B3 + 32)                // 167968
#define SM_ZP  (SM_X + NWARPS*16*8*4)      // 178208: [wid][e(8)+side*8][lane] f32
#define SMEM_BYTES (SM_ZP + NWARPS*512*4)  // 219168

// ---- MUFU approx primitives ----
__device__ __forceinline__ float fast_rcp(float x) {
    float r; asm("rcp.approx.f32 %0, %1;" : "=f"(r) : "f"(x)); return r;
}
__device__ __forceinline__ float fast_rsqrt(float x) {
    float r; asm("rsqrt.approx.f32 %0, %1;" : "=f"(r) : "f"(x)); return r;
}
__device__ __forceinline__ float fast_sqrt(float x) {
    float r; asm("sqrt.approx.f32 %0, %1;" : "=f"(r) : "f"(x)); return r;
}
__device__ __forceinline__ float fast_log(float x) {
    float l; asm("lg2.approx.f32 %0, %1;" : "=f"(l) : "f"(x)); return l * LN2;
}
__device__ __forceinline__ float fast_ex2(float s) {
    float e; asm("ex2.approx.f32 %0, %1;" : "=f"(e) : "f"(s)); return e;
}

// Quad-batched r_i = 1/(ex2(s_i)+1), one rcp for four values.
__device__ __forceinline__ void quad_r(float s0, float s1, float s2, float s3,
                                       float& r0, float& r1, float& r2, float& r3)
{
    float e0p = fast_ex2(s0) + 1.0f;
    float e1p = fast_ex2(s1) + 1.0f;
    float e2p = fast_ex2(s2) + 1.0f;
    float e3p = fast_ex2(s3) + 1.0f;
    float pa = e0p * e1p, pb = e2p * e3p;
    float q  = fast_rcp(pa * pb);
    float qa = q * pb, qb = q * pa;
    r0 = qa * e1p;  r1 = qa * e0p;
    r2 = qb * e3p;  r3 = qb * e2p;
}

// ---- bf16x2 pack + hi/lo split ----
__device__ __forceinline__ void split2(float v0, float v1, uint32_t& hi, uint32_t& lo) {
    __nv_bfloat162 h = __floats2bfloat162_rn(v0, v1);
    hi = *reinterpret_cast<uint32_t*>(&h);
    float f0 = __uint_as_float(hi << 16);
    float f1 = __uint_as_float(hi & 0xffff0000u);
    __nv_bfloat162 l = __floats2bfloat162_rn(v0 - f0, v1 - f1);
    lo = *reinterpret_cast<uint32_t*>(&l);
}

// ---- mma.sync m16n8k16 / m16n8k8, bf16, fp32 accum ----
__device__ __forceinline__ void mma16816(float& c0, float& c1, float& c2, float& c3,
    uint32_t a0, uint32_t a1, uint32_t a2, uint32_t a3, uint32_t b0, uint32_t b1)
{
    asm volatile("mma.sync.aligned.m16n8k16.row.col.f32.bf16.bf16.f32 "
        "{%0,%1,%2,%3},{%4,%5,%6,%7},{%8,%9},{%0,%1,%2,%3};"
        : "+f"(c0), "+f"(c1), "+f"(c2), "+f"(c3)
        : "r"(a0), "r"(a1), "r"(a2), "r"(a3), "r"(b0), "r"(b1));
}
__device__ __forceinline__ void mma16808(float& c0, float& c1, float& c2, float& c3,
    uint32_t a0, uint32_t a1, uint32_t b0)
{
    asm volatile("mma.sync.aligned.m16n8k8.row.col.f32.bf16.bf16.f32 "
        "{%0,%1,%2,%3},{%4,%5},{%6},{%0,%1,%2,%3};"
        : "+f"(c0), "+f"(c1), "+f"(c2), "+f"(c3)
        : "r"(a0), "r"(a1), "r"(b0));
}

// Light vstar-only shock (invariants hoisted). 9 MUFU.
__device__ __forceinline__ float vstar_light(float pC, float p, float v, float sgn,
    float rrho, float omv2, float h, float hW, float a2, float irW)
{
    float dp   = p - pC;
    float rpC  = fast_rcp(pC);
    float t04  = 0.4f * dp * rpC;
    float A    = 1.0f + t04;
    float C    = h * dp * rrho - h * h;
    float disc = fmaxf(fmaf(t04, t04, -4.0f * A * C), 0.0f);
    float hC   = (fast_sqrt(disc) + t04) * (0.5f * fast_rcp(A));
    float hCm1 = hC - 1.0f;
    float denj = h * rrho - 0.4f * hC * hCm1 * rpC;
    float j2   = fmaxf((pC - p) * fast_rcp(denj), 1e-12f);
    float rj   = fast_rsqrt(j2);
    float jabs = j2 * rj;
    float Vs   = (a2 * v + sgn * jabs * fast_sqrt(fmaf(a2, omv2, j2))) * fast_rcp(a2 + j2);
    float Ws   = fast_rsqrt(fmaxf(1.0f - Vs * Vs, 1e-12f));
    float rjs  = sgn * rj;
    float num  = hW * v + Ws * (pC - p) * rjs;
    float den  = hW + (pC - p) * (Ws * v * rjs + irW);
    return num * fast_rcp(den);
}

// Full shock (final recompute only).
__device__ __forceinline__ void get_vel_shock(
    float pC, float rho, float p, float v, float sign,
    float& rhoC, float& hC, float& vstar, float& Vs)
{
    float rrho = fast_rcp(rho);
    float h    = fmaf(2.5f * p, rrho, 1.0f);
    float omv2 = 1.0f - v * v;
    float W    = fast_rsqrt(omv2);
    float dp   = p - pC;
    float rpC  = fast_rcp(pC);
    float t04  = 0.4f * dp * rpC;
    float A    = 1.0f + t04;
    float B    = -t04;
    float C    = h * dp * rrho - h * h;
    float disc = fmaxf(fmaf(B, B, -4.0f * A * C), 0.0f);
    hC   = (fast_sqrt(disc) - B) * (0.5f * fast_rcp(A));
    float hCm1 = hC - 1.0f;
    rhoC = 2.5f * pC * fast_rcp(hCm1);
    float denj = h * rrho - 0.4f * hC * hCm1 * rpC;
    float j2   = fmaxf((pC - p) * fast_rcp(denj), 1e-12f);
    float jabs = fast_sqrt(j2);
    float rw   = rho * W;
    float a2   = rw * rw;
    Vs = (a2 * v + sign * jabs * fast_sqrt(fmaf(a2, omv2, j2))) * fast_rcp(a2 + j2);
    float Ws = fast_rsqrt(fmaxf(1.0f - Vs * Vs, 1e-12f));
    float js = sign * jabs;
    float rjs = fast_rcp(js);
    float hW  = h * W;
    float num = hW * v + Ws * (pC - p) * rjs;
    float den = hW + (pC - p) * (Ws * v * rjs + rrho * omv2 * W);
    vstar = num * fast_rcp(den);
}

// ---- prep: build packed fragment tables (all scales + affine folds) ----
__global__ void prep_kernel(const float* __restrict__ W1, const float* __restrict__ W2,
                            const float* __restrict__ b1, const float* __restrict__ b2,
                            const float* __restrict__ W3, const float* __restrict__ b3)
{
    const int nW2 = NENS*8*4*32, nW1 = NENS*8*32, nBW = NENS*8*4;
    int idx = blockIdx.x * blockDim.x + threadIdx.x;
    if (idx < nW2) {                               // B-frags of (-2*TANH_C*W2)
        int lane = idx & 31, kt = (idx >> 5) & 3, nt = (idx >> 7) & 7, e = idx >> 10;
        int gg = lane >> 2, t = lane & 3;
        int n = nt * 8 + gg;
        int kb = kt * 16 + 2 * t;
        const float s = -2.0f * TANH_C;
        float w00 = s * W2[(e*HID + kb    )*HID + n], w01 = s * W2[(e*HID + kb + 1)*HID + n];
        float w10 = s * W2[(e*HID + kb + 8)*HID + n], w11 = s * W2[(e*HID + kb + 9)*HID + n];
        uint32_t h0, l0, h1, l1;
        split2(w00, w01, h0, l0);
        split2(w10, w11, h1, l1);
        g_w2p[idx] = make_uint4(h0, h1, l0, l1);
    } else if (idx < nW2 + nW1) {                  // W1 packed + bias (TANH_C-scaled)
        int j = idx - nW2;
        int lane = j & 31, nt = (j >> 5) & 7, e = j >> 8;
        int gg = lane >> 2, t = lane & 3;
        int n = nt * 8 + gg;
        int k = 2 * t;
        float w0 = (k     < 6) ? TANH_C * W1[(e*6 + k    )*HID + n] : 0.0f;
        float w1 = (k + 1 < 6) ? TANH_C * W1[(e*6 + k + 1)*HID + n] : 0.0f;
        uint32_t h0, l0;
        split2(w0, w1, h0, l0);
        float bias0 = TANH_C * b1[e*HID + nt*8 + 2*t];
        float bias1 = TANH_C * b1[e*HID + nt*8 + 2*t + 1];
        g_w1p[j] = make_uint4(h0, l0, __float_as_uint(bias0), __float_as_uint(bias1));
    } else if (idx < nW2 + nW1 + nBW) {            // b2' = TANH_C*(b2 + colsum W2); w3' = -2*log2e*w3
        int j = idx - nW2 - nW1;
        int t = j & 3, nt = (j >> 2) & 7, e = j >> 5;
        int base = e*HID + nt*8 + 2*t;
        float cs0 = b2[base], cs1 = b2[base + 1];
        for (int k = 0; k < HID; k++) {
            cs0 += W2[(e*HID + k)*HID + (nt*8 + 2*t)];
            cs1 += W2[(e*HID + k)*HID + (nt*8 + 2*t + 1)];
        }
        g_bw[j] = make_float4(TANH_C * cs0, TANH_C * cs1,
                              -2.0f * LOG2E * W3[base], -2.0f * LOG2E * W3[base+1]);
    } else if (idx < nW2 + nW1 + nBW + NENS) {     // b3' = log2e*(b3 + sum w3)
        int e = idx - nW2 - nW1 - nBW;
        float s = b3[e];
        for (int j = 0; j < HID; j++) s += W3[e*HID + j];
        g_b3s[e] = LOG2E * s;
    }
}

__global__ void __launch_bounds__(NTHREADS, 1)
solver_mma(const float* __restrict__ P, const float* __restrict__ F,
           float* __restrict__ out, int N)
{
    extern __shared__ char smem[];
    uint4*  sW2p = (uint4*)(smem + SM_W2P);
    uint4*  sW1p = (uint4*)(smem + SM_W1P);
    float4* sBW  = (float4*)(smem + SM_BW);
    float*  sB3  = (float*)(smem + SM_B3);
    float*  sX   = (float*)(smem + SM_X);

    // cooperative smem fill
    {
        const int4* s1 = (const int4*)g_w2p;  int4* d1 = (int4*)sW2p;
        for (int i = threadIdx.x; i < NENS*8*4*32; i += NTHREADS) d1[i] = s1[i];
        const int4* s2 = (const int4*)g_w1p;  int4* d2 = (int4*)sW1p;
        for (int i = threadIdx.x; i < NENS*8*32; i += NTHREADS) d2[i] = s2[i];
        const int4* s3 = (const int4*)g_bw;   int4* d3 = (int4*)sBW;
        for (int i = threadIdx.x; i < NENS*8*4; i += NTHREADS) d3[i] = s3[i];
        if (threadIdx.x < NENS) sB3[threadIdx.x] = g_b3s[threadIdx.x];
    }
    __syncthreads();

    const int lane = threadIdx.x & 31, wid = threadIdx.x >> 5;
    const int g = lane >> 2, t = lane & 3;
    const int side = lane >> 4;          // 0 = Left state, 1 = Right state
    const int c    = lane & 15;          // cell index within tile
    const float sgn = side ? 1.0f : -1.0f;
    const int ntiles = (N + 15) >> 4;
    float* Xw  = sX + wid * 128;
    float* ZPw = (float*)(smem + SM_ZP) + wid * 512;   // [e + side8*8][lane]

    for (int tile = blockIdx.x * NWARPS + wid; tile < ntiles; tile += gridDim.x * NWARPS) {
        const int cell = tile * 16 + c;
        const bool act = (cell < N);

        // each lane owns ONE side of one cell; prefetch flux early
        float rho = 1.0f, p = 1.0f, v = 0.0f;
        float fx0 = 0.0f, fx1 = 0.0f, fx2 = 0.0f;
        if (act) {
            rho = P[cell*6 + side];
            p   = P[cell*6 + 2 + side];
            v   = P[cell*6 + 4 + side];
            fx0 = F[cell*6 + side];
            fx1 = F[cell*6 + 2 + side];
            fx2 = F[cell*6 + 4 + side];
            Xw[c*8 + side]     = fast_log(rho);
            Xw[c*8 + 2 + side] = fast_log(p);
            Xw[c*8 + 4 + side] = v;
        } else {
            Xw[c*8 + side]     = 0.0f;
            Xw[c*8 + 2 + side] = 0.0f;
            Xw[c*8 + 4 + side] = 0.0f;
        }
        if (side == 0) { Xw[c*8 + 6] = 0.0f; Xw[c*8 + 7] = 0.0f; }
        __syncwarp();
        const float aPress = fmaxf(p, __shfl_xor_sync(0xffffffffu, p, 16));

        // per-lane shock invariants
        const float rrho = fast_rcp(rho);
        const float omv2 = 1.0f - v * v;
        const float Wl   = fast_rsqrt(omv2);
        const float hh   = fmaf(2.5f * p, rrho, 1.0f);
        const float hW   = hh * Wl;
        const float rw   = rho * Wl;
        const float a2   = rw * rw;
        const float irW  = rrho * omv2 * Wl;

        // layer1 A-fragments
        uint32_t a1h0, a1l0, a1h1, a1l1;
        {
            float2 f  = *(float2*)&Xw[g*8 + 2*t];
            float2 f8 = *(float2*)&Xw[(g+8)*8 + 2*t];
            split2(f.x,  f.y,  a1h0, a1l0);
            split2(f8.x, f8.y, a1h1, a1l1);
        }
        __syncwarp();

        // ================= MLP loop: pure mma + activations, tail deferred ==
        for (int e = 0; e < NENS; e++) {
            // ---- layer 1: X[16x8] @ W1[8x64] via m16n8k8 ----
            uint32_t A2h[4][4], A2l[4][4];
            const uint4* w1p = sW1p + (e * 8) * 32 + lane;
            #pragma unroll
            for (int nt = 0; nt < 8; nt++) {
                uint4 w = w1p[nt * 32];
                float cH0 = __uint_as_float(w.z), cH1 = __uint_as_float(w.w);
                float cH2 = cH0, cH3 = cH1;
                float cM0=0,cM1=0,cM2=0,cM3=0;
                mma16808(cH0,cH1,cH2,cH3, a1h0,a1h1, w.x);
                mma16808(cM0,cM1,cM2,cM3, a1h0,a1h1, w.y);
                mma16808(cM0,cM1,cM2,cM3, a1l0,a1l1, w.x);
                float r0, r1, r2, r3;
                quad_r(cH0+cM0, cH1+cM1, cH2+cM2, cH3+cM3, r0, r1, r2, r3);
                int kt = nt >> 1, hhp = (nt & 1) * 2;
                split2(r0, r1, A2h[kt][hhp],     A2l[kt][hhp]);
                split2(r2, r3, A2h[kt][hhp + 1], A2l[kt][hhp + 1]);
            }

            // ---- layers 2+3 ----
            float zp0 = 0.0f, zp1 = 0.0f;
            const uint4* w2p = sW2p + (e * 8) * 4 * 32 + lane;
            #pragma unroll 2
            for (int nt = 0; nt < 8; nt++) {
                float4 bw = sBW[(e*8 + nt)*4 + t];
                float cH0=bw.x, cH1=bw.y, cH2=bw.x, cH3=bw.y;
                float cM0=0,cM1=0,cM2=0,cM3=0;
                float cL0=0,cL1=0,cL2=0,cL3=0;
                const uint4* wrow = w2p + nt * (4*32);
                #pragma unroll
                for (int kt = 0; kt < 4; kt++) {
                    uint4 w = wrow[kt * 32];
                    mma16816(cH0,cH1,cH2,cH3, A2h[kt][0],A2h[kt][1],A2h[kt][2],A2h[kt][3], w.x,w.y);
                    mma16816(cM0,cM1,cM2,cM3, A2h[kt][0],A2h[kt][1],A2h[kt][2],A2h[kt][3], w.z,w.w);
                    mma16816(cL0,cL1,cL2,cL3, A2l[kt][0],A2l[kt][1],A2l[kt][2],A2l[kt][3], w.x,w.y);
                }
                float r0, r1, r2, r3;
                quad_r(cH0+cM0+cL0, cH1+cM1+cL1, cH2+cM2+cL2, cH3+cM3+cL3,
                       r0, r1, r2, r3);
                zp0 = fmaf(r0, bw.z, zp0); zp0 = fmaf(r1, bw.w, zp0);
                zp1 = fmaf(r2, bw.z, zp1); zp1 = fmaf(r3, bw.w, zp1);
            }
            // stash partials; ALL reductions + shocks deferred past the loop
            ZPw[e*32 + lane]       = zp0;
            ZPw[256 + e*32 + lane] = zp1;
        }
        __syncwarp();

        // ============ deferred tail: 8 reductions + 8 shocks, full ILP =====
        float zA[NENS], zB[NENS];
        #pragma unroll
        for (int e = 0; e < NENS; e++) {
            zA[e] = ZPw[e*32 + lane];
            zB[e] = ZPw[256 + e*32 + lane];
        }
        #pragma unroll
        for (int e = 0; e < NENS; e++) {
            zA[e] += __shfl_xor_sync(0xffffffffu, zA[e], 1);
            zB[e] += __shfl_xor_sync(0xffffffffu, zB[e], 1);
        }
        #pragma unroll
        for (int e = 0; e < NENS; e++) {
            zA[e] += __shfl_xor_sync(0xffffffffu, zA[e], 2);
            zB[e] += __shfl_xor_sync(0xffffffffu, zB[e], 2);
        }
        const int src = (c & 7) * 4;
        float pc[NENS];
        #pragma unroll
        for (int e = 0; e < NENS; e++) {
            float za = __shfl_sync(0xffffffffu, zA[e], src);
            float zb = __shfl_sync(0xffffffffu, zB[e], src);
            float z  = ((c < 8) ? za : zb) + sB3[e];   // log2e-scaled
            pc[e] = aPress * fmaf(2.0f, fast_ex2(z), 1.0f);
        }
        float vs[NENS];
        #pragma unroll
        for (int e = 0; e < NENS; e++)
            vs[e] = vstar_light(pc[e], p, v, sgn, rrho, omv2, hh, hW, a2, irW);

        float bestdiff = 3.4e38f, bestP = 0.0f;
        #pragma unroll
        for (int e = 0; e < NENS; e++) {
            float vsO = __shfl_xor_sync(0xffffffffu, vs[e], 16);
            float d = fabsf(vs[e] - vsO);     // symmetric: both lanes agree
            if (d < bestdiff) { bestdiff = d; bestP = pc[e]; }
        }

        // final shock recompute, parallel over sides; exchange via shfl
        float rhoC, hC, vstar, vsh;
        get_vel_shock(bestP, rho, p, v, sgn, rhoC, hC, vstar, vsh);
        float vstarO = __shfl_xor_sync(0xffffffffu, vstar, 16);
        float vshO   = __shfl_xor_sync(0xffffffffu, vsh,   16);
        float rhoCO  = __shfl_xor_sync(0xffffffffu, rhoC,  16);
        float hCO    = __shfl_xor_sync(0xffffffffu, hC,    16);
        float fR0    = __shfl_xor_sync(0xffffffffu, fx0,   16);
        float fR1    = __shfl_xor_sync(0xffffffffu, fx1,   16);
        float fR2    = __shfl_xor_sync(0xffffffffu, fx2,   16);

        if (side == 0 && act) {
            float lam = 0.5f * (vstarO + vstar);
            float WC  = fast_rsqrt(1.0f - lam * lam);
            float densCL = WC * rhoC, densCR = WC * rhoCO;

            float f0 = 0.0f, f1 = 0.0f, f2 = 0.0f;
            if (vsh >= 0.0f) { f0 = fx0; f1 = fx1; f2 = fx2; }
            if (vsh < 0.0f && lam > 0.0f) {
                f0 = densCL * lam;
                f1 = densCL * (WC * hC - 1.0f) * lam;
                f2 = (WC * WC * rhoC * hC * lam) * lam + bestP;
            }
            if (lam <= 0.0f && vshO > 0.0f) {
                f0 = densCR * lam;
                f1 = densCR * (WC * hCO - 1.0f) * lam;
                f2 = (WC * WC * rhoCO * hCO * lam) * lam + bestP;
            }
            if (vshO <= 0.0f) { f0 = fR0; f1 = fR1; f2 = fR2; }
            out[cell*3+0] = f0; out[cell*3+1] = f1; out[cell*3+2] = f2;
        }
    }
}

extern "C" void kernel_launch(void* const* d_in, const int* in_sizes, int n_in,
                              void* d_out, int out_size)
{
    const float* P  = (const float*)d_in[0];
    const float* F  = (const float*)d_in[2];
    const float* W1 = (const float*)d_in[5];
    const float* b1 = (const float*)d_in[6];
    const float* W2 = (const float*)d_in[7];
    const float* b2 = (const float*)d_in[8];
    const float* W3 = (const float*)d_in[9];
    const float* b3 = (const float*)d_in[10];
    float* out = (float*)d_out;
    const int N = in_sizes[0] / 6;

    const int nprep = NENS*8*4*32 + NENS*8*32 + NENS*8*4 + NENS;
    prep_kernel<<<(nprep + 255) / 256, 256>>>(W1, W2, b1, b2, W3, b3);

    cudaFuncSetAttribute(solver_mma,
                         cudaFuncAttributeMaxDynamicSharedMemorySize, SMEM_BYTES);
    solver_mma<<<148, NTHREADS, SMEM_BYTES>>>(P, F, out, N);
}